// round 13
// baseline (speedup 1.0000x reference)
#include <cuda_runtime.h>
#include <cuda_bf16.h>
#include <math.h>
#include <stdint.h>

#define Bsz   128
#define Wd    128
#define FIN   64
#define NN    64
#define EE    4096
#define EDd   16
#define HC    128
#define FLATd 8192
#define HIDd  2048
#define SPLITK 16
#define EVW   132
#define NPB   4      // nodes per k_agg block

// ---------------- scratch ----------------
__device__ __align__(128) float g_xg[Bsz * NN * Wd];
__device__ __align__(128) float g_h[Bsz * NN * HC];
__device__ __align__(128) uint32_t g_x_hi[Bsz * (FLATd / 2)];
__device__ __align__(128) uint32_t g_x_lo[Bsz * (FLATd / 2)];
__device__ __align__(128) float g_h1part[SPLITK * Bsz * HIDd];
__device__ __align__(128) float g_h1[Bsz * HIDd];
__device__ __align__(128) float g_score[Bsz * EE * 4];   // [b][csr_pos][h]
__device__ int  g_csr_off[NN + 1];
__device__ int2 g_csr_es[EE];
__device__ int  g_pos[EE];

// ---------------- helpers ----------------
__device__ __forceinline__ uint32_t smem_u32(const void* p) {
    uint32_t a;
    asm("{ .reg .u64 t; cvta.to.shared.u64 t, %1; cvt.u32.u64 %0, t; }" : "=r"(a) : "l"(p));
    return a;
}
__device__ __forceinline__ void ldm_x4(uint32_t (&r)[4], uint32_t addr) {
    asm volatile("ldmatrix.sync.aligned.m8n8.x4.shared.b16 {%0,%1,%2,%3}, [%4];"
        : "=r"(r[0]), "=r"(r[1]), "=r"(r[2]), "=r"(r[3]) : "r"(addr));
}
__device__ __forceinline__ void mma_bf16(float (&d)[4], const uint32_t (&a)[4],
                                         uint32_t b0, uint32_t b1) {
    asm volatile(
        "mma.sync.aligned.m16n8k16.row.col.f32.bf16.bf16.f32 "
        "{%0,%1,%2,%3}, {%4,%5,%6,%7}, {%8,%9}, {%0,%1,%2,%3};"
        : "+f"(d[0]), "+f"(d[1]), "+f"(d[2]), "+f"(d[3])
        : "r"(a[0]), "r"(a[1]), "r"(a[2]), "r"(a[3]), "r"(b0), "r"(b1));
}
__device__ __forceinline__ void cvtpair(float a, float b, uint32_t& hi, uint32_t& lo) {
    __nv_bfloat16 ha = __float2bfloat16(a), hb2 = __float2bfloat16(b);
    float ra = a - __bfloat162float(ha), rb = b - __bfloat162float(hb2);
    __nv_bfloat16 la = __float2bfloat16(ra), lb = __float2bfloat16(rb);
    hi = (uint32_t)__bfloat16_as_ushort(ha) | ((uint32_t)__bfloat16_as_ushort(hb2) << 16);
    lo = (uint32_t)__bfloat16_as_ushort(la) | ((uint32_t)__bfloat16_as_ushort(lb) << 16);
}
__device__ __forceinline__ void sts_v2(uint32_t addr, uint32_t x, uint32_t y) {
    asm volatile("st.shared.v2.b32 [%0], {%1,%2};" :: "r"(addr), "r"(x), "r"(y) : "memory");
}
typedef unsigned long long u64;
__device__ __forceinline__ void sts64(uint32_t addr, u64 v) {
    asm volatile("st.shared.b64 [%0], %1;" :: "r"(addr), "l"(v) : "memory");
}
__device__ __forceinline__ u64 pkx2(float lo, float hi) {
    u64 r; asm("mov.b64 %0, {%1,%2};" : "=l"(r) : "f"(lo), "f"(hi)); return r;
}
__device__ __forceinline__ u64 addx2(u64 a, u64 b) {
    u64 d; asm("add.rn.f32x2 %0, %1, %2;" : "=l"(d) : "l"(a), "l"(b)); return d;
}
__device__ __forceinline__ u64 mulx2(u64 a, u64 b) {
    u64 d; asm("mul.rn.f32x2 %0, %1, %2;" : "=l"(d) : "l"(a), "l"(b)); return d;
}
__device__ __forceinline__ u64 fmax2(u64 a, u64 b, u64 c) {
    u64 d; asm("fma.rn.f32x2 %0, %1, %2, %3;" : "=l"(d) : "l"(a), "l"(b), "l"(c)); return d;
}
__device__ __forceinline__ float2 upkx2(u64 v) {
    float2 r; asm("mov.b64 {%0,%1}, %2;" : "=f"(r.x), "=f"(r.y) : "l"(v)); return r;
}

// ---------------- CSR build (+ position map) ----------------
__global__ void k_csr(const int* __restrict__ ei) {
    __shared__ int cnt[NN];
    __shared__ int off[NN + 1];
    __shared__ int cur[NN];
    int tid = threadIdx.x;
    if (tid < NN) cnt[tid] = 0;
    __syncthreads();
    for (int e = tid; e < EE; e += blockDim.x)
        atomicAdd(&cnt[ei[EE + e]], 1);
    __syncthreads();
    if (tid == 0) {
        int run = 0;
        for (int k = 0; k < NN; k++) { off[k] = run; cur[k] = run; run += cnt[k]; }
        off[NN] = run;
    }
    __syncthreads();
    for (int e = tid; e < EE; e += blockDim.x) {
        int d = ei[EE + e];
        int pos = atomicAdd(&cur[d], 1);
        g_csr_es[pos] = make_int2(e, ei[e]);
        g_pos[e] = pos;
    }
    if (tid <= NN) g_csr_off[tid] = off[tid];
}

// ---------------- TCN conv1d(k=3,pad=1) ----------------
__global__ void k_tcn(const float* __restrict__ x,
                      const float* __restrict__ tw,
                      const float* __restrict__ tb) {
    __shared__ float xs[FIN * 129];
    __shared__ float sw[16 * 192];
    int b = blockIdx.y, nc = blockIdx.x;
    int tid = threadIdx.x;
    const float* xb = x + (size_t)b * Wd * FIN;
    for (int idx = tid; idx < Wd * FIN; idx += 128) {
        int w = idx >> 6, i = idx & 63;
        xs[i * 129 + w] = xb[idx];
    }
    for (int idx = tid; idx < 16 * 192; idx += 128)
        sw[idx] = tw[nc * 16 * 192 + idx];
    __syncthreads();
    int w = tid;
    float acc[16];
#pragma unroll
    for (int nl = 0; nl < 16; nl++) acc[nl] = tb[nc * 16 + nl];
    for (int i = 0; i < FIN; i++) {
        float x0 = xs[i * 129 + w];
        float xm = (w > 0)   ? xs[i * 129 + w - 1] : 0.f;
        float xp = (w < 127) ? xs[i * 129 + w + 1] : 0.f;
#pragma unroll
        for (int nl = 0; nl < 16; nl++) {
            const float* wp = &sw[nl * 192 + i * 3];
            acc[nl] += xm * wp[0] + x0 * wp[1] + xp * wp[2];
        }
    }
#pragma unroll
    for (int nl = 0; nl < 16; nl++)
        g_xg[((size_t)b * NN + nc * 16 + nl) * Wd + w] = acc[nl];
}

// ---------------- lin_l projection ----------------
__global__ void k_linl(const float* __restrict__ lw, const float* __restrict__ lb) {
    __shared__ float xs[NN * 129];
    __shared__ float ws[64 * 33];
    int b = blockIdx.y, oc = blockIdx.x;
    int tid = threadIdx.x;
    for (int idx = tid; idx < NN * Wd; idx += 256) {
        int n = idx >> 7, w = idx & 127;
        xs[n * 129 + w] = g_xg[(size_t)b * NN * Wd + idx];
    }
    int tx = tid & 15, ty = tid >> 4;
    float acc[4][4];
#pragma unroll
    for (int i = 0; i < 4; i++)
#pragma unroll
        for (int j = 0; j < 4; j++) acc[i][j] = 0.f;
    for (int wc = 0; wc < 4; wc++) {
        __syncthreads();
        for (int idx = tid; idx < 64 * 32; idx += 256) {
            int ol = idx >> 5, wl = idx & 31;
            ws[ol * 33 + wl] = lw[(oc * 64 + ol) * Wd + wc * 32 + wl];
        }
        __syncthreads();
#pragma unroll 4
        for (int wl = 0; wl < 32; wl++) {
            float a[4], bb[4];
#pragma unroll
            for (int j = 0; j < 4; j++) a[j]  = xs[(ty * 4 + j) * 129 + wc * 32 + wl];
#pragma unroll
            for (int j = 0; j < 4; j++) bb[j] = ws[(tx * 4 + j) * 33 + wl];
#pragma unroll
            for (int i = 0; i < 4; i++)
#pragma unroll
                for (int j = 0; j < 4; j++) acc[i][j] += a[i] * bb[j];
        }
    }
#pragma unroll
    for (int i = 0; i < 4; i++)
#pragma unroll
        for (int j = 0; j < 4; j++) {
            int n = ty * 4 + i, o = oc * 64 + tx * 4 + j;
            g_h[((size_t)b * NN + n) * HC + o] = acc[i][j] + lb[o];
        }
}

// ---------------- k_score: R10 single-pass, CSR-ordered writes ----------------
__global__ void __launch_bounds__(256) k_score(const int* __restrict__ ei,
                       const float* __restrict__ eattr,
                       const float* __restrict__ lew,
                       const float* __restrict__ leb,
                       const float* __restrict__ att) {
    __shared__ uint32_t bfrag[2][2][4][2][32];       // [hi/lo][eh][nt][reg][lane]
    __shared__ __align__(16) float ev_s[64 * EVW];
    __shared__ int src_s[64], dst_s[64], pos_s[64];

    int e0 = blockIdx.x << 6, b = blockIdx.y;
    int t = threadIdx.x, lane = t & 31, w = t >> 5;
    int wq = w & 1, wc = w >> 1;
    int g = lane >> 2, tq = lane & 3;

    // A fragments
    uint32_t Ah[2][4], Al[2][4];
#pragma unroll
    for (int mt = 0; mt < 2; mt++) {
        int ch0 = wc * 32 + mt * 16 + g;
        const float* wr0 = lew + ch0 * EDd;
        const float* wr1 = lew + (ch0 + 8) * EDd;
        float2 p0 = *(const float2*)(wr0 + 2 * tq);
        float2 p1 = *(const float2*)(wr1 + 2 * tq);
        float2 p2 = *(const float2*)(wr0 + 2 * tq + 8);
        float2 p3 = *(const float2*)(wr1 + 2 * tq + 8);
        cvtpair(p0.x, p0.y, Ah[mt][0], Al[mt][0]);
        cvtpair(p1.x, p1.y, Ah[mt][1], Al[mt][1]);
        cvtpair(p2.x, p2.y, Ah[mt][2], Al[mt][2]);
        cvtpair(p3.x, p3.y, Ah[mt][3], Al[mt][3]);
    }

    if (t < 64) {
        src_s[t] = ei[e0 + t];
        dst_s[t] = ei[EE + e0 + t];
        pos_s[t] = g_pos[e0 + t];
    }
    // stage ea -> bf16 hi/lo B-fragments
    {
        int j = t >> 2, q = t & 3;
        const float* row = eattr + (size_t)b * EE * EDd + (size_t)(e0 + j) * EDd;
        float4 ea4 = *(const float4*)(row + q * 4);
        uint32_t h0, l0, h1, l1;
        cvtpair(ea4.x, ea4.y, h0, l0);
        cvtpair(ea4.z, ea4.w, h1, l1);
        int eh = j >> 5, j32 = j & 31;
        int nt = j32 >> 3, reg = q >> 1;
        int lpos = (j32 & 7) * 4 + (q & 1) * 2;
        bfrag[0][eh][nt][reg][lpos] = h0; bfrag[0][eh][nt][reg][lpos + 1] = h1;
        bfrag[1][eh][nt][reg][lpos] = l0; bfrag[1][eh][nt][reg][lpos + 1] = l1;
    }
    __syncthreads();

    // mma: warp (wq, wc): its 32 channels for its 32 edges
#pragma unroll
    for (int nt = 0; nt < 4; nt++) {
        uint32_t b0h = bfrag[0][wq][nt][0][lane], b1h = bfrag[0][wq][nt][1][lane];
        uint32_t b0l = bfrag[1][wq][nt][0][lane], b1l = bfrag[1][wq][nt][1][lane];
#pragma unroll
        for (int mt = 0; mt < 2; mt++) {
            float a4[4] = {0.f, 0.f, 0.f, 0.f};
            mma_bf16(a4, Ah[mt], b0h, b1h);
            mma_bf16(a4, Ah[mt], b0l, b1l);
            mma_bf16(a4, Al[mt], b0h, b1h);
            int ch = wc * 32 + mt * 16 + g;
            int el = wq * 32 + nt * 8 + 2 * tq;
            ev_s[el * EVW + ch]           = a4[0];
            ev_s[(el + 1) * EVW + ch]     = a4[1];
            ev_s[el * EVW + ch + 8]       = a4[2];
            ev_s[(el + 1) * EVW + ch + 8] = a4[3];
        }
    }
    __syncthreads();

    // epilogue: f32x2 over channel pairs, att folded into lrelu constants
    {
        int pp = t & 63, g4 = t >> 6;
        const float* hb = g_h + (size_t)b * NN * HC;
        u64 att2 = *(const u64*)(att + 2 * pp);
        u64 eb2  = *(const u64*)(leb + 2 * pp);
        u64 aC1 = mulx2(att2, pkx2(0.505f, 0.505f));
        u64 aC2 = mulx2(att2, pkx2(0.495f, 0.495f));
        const u64 MSK = 0x7FFFFFFF7FFFFFFFull;
#pragma unroll 4
        for (int r = 0; r < 16; r++) {
            int e = g4 * 16 + r;
            int s = src_s[e], d = dst_s[e];
            u64 hs2 = *(const u64*)(hb + s * HC + 2 * pp);
            u64 hd2 = *(const u64*)(hb + d * HC + 2 * pp);
            u64 ev2 = *(const u64*)&ev_s[e * EVW + 2 * pp];
            u64 z = addx2(addx2(hs2, hd2), addx2(ev2, eb2));
            u64 az; asm("and.b64 %0, %1, %2;" : "=l"(az) : "l"(z), "l"(MSK));
            *(u64*)&ev_s[e * EVW + 2 * pp] = fmax2(az, aC2, mulx2(z, aC1));
        }
    }
    __syncthreads();

    // reduce: thread (e = t&63, h = t>>6) sums 32 channels -> score at CSR position
    {
        int e = t & 63, h = t >> 6;
        const float* rp = &ev_s[e * EVW + h * 32];
        float s0 = 0.f, s1 = 0.f, s2 = 0.f, s3 = 0.f;
#pragma unroll
        for (int c4 = 0; c4 < 8; c4++) {
            float4 v = *(const float4*)(rp + c4 * 4);
            s0 += v.x; s1 += v.y; s2 += v.z; s3 += v.w;
        }
        g_score[((size_t)b * EE + pos_s[e]) * 4 + h] = (s0 + s1) + (s2 + s3);
    }
}

// ---------------- k_agg v3: 4 nodes/block, smem-staged g_h[b], LDS-only aggregation ----------------
__global__ void __launch_bounds__(256) k_agg() {
    __shared__ __align__(16) float hsm[NN * HC];   // 32 KB: whole g_h[b]
    __shared__ int    srcs[128];
    __shared__ float4 sc_s[128];
    __shared__ float  alpha_s[4][128];
    __shared__ float  resc_s[4];
    __shared__ float  den_s[4];
    __shared__ u64    accbuf[3][64];

    int ng = blockIdx.x, b = blockIdx.y;
    int t = threadIdx.x, lane = t & 31, h = t >> 5;   // h valid for t<128
    int pp = t & 63, q = t >> 6, h2 = pp >> 4;

    // stage g_h[b] -> smem (coalesced u64 burst, MLP=16)
    {
        const u64* src = (const u64*)(g_h + (size_t)b * NN * HC);
        u64* dst = (u64*)hsm;
        for (int i = t; i < NN * HC / 2; i += 256)
            dst[i] = src[i];
    }
    __syncthreads();

    for (int k = 0; k < NPB; k++) {
        int n = ng * NPB + k;
        int beg = g_csr_off[n], end = g_csr_off[n + 1];
        int deg = end - beg;
        const int2* lst = g_csr_es + beg;
        const float4* scb = (const float4*)g_score + (size_t)b * EE + beg;

        float m = -1e30f, den = 0.f;
        u64 acc2 = 0ull;

        for (int base = 0; base < deg; base += 128) {
            int cnt = min(128, deg - base);
            if (t < cnt) {
                srcs[t] = lst[base + t].y;
                sc_s[t] = scb[base + t];      // coalesced (CSR-ordered scores)
            }
            __syncthreads();

            if (t < 128) {   // softmax: warps 0-3, one head each
                float sl[4];
#pragma unroll
                for (int r = 0; r < 4; r++) {
                    int jj = lane + r * 32;
                    sl[r] = (jj < cnt) ? ((const float*)&sc_s[jj])[h] : -1e30f;
                }
                float cm = fmaxf(fmaxf(sl[0], sl[1]), fmaxf(sl[2], sl[3]));
                cm = fmaxf(cm, __shfl_xor_sync(0xffffffffu, cm, 16));
                cm = fmaxf(cm, __shfl_xor_sync(0xffffffffu, cm, 8));
                cm = fmaxf(cm, __shfl_xor_sync(0xffffffffu, cm, 4));
                cm = fmaxf(cm, __shfl_xor_sync(0xffffffffu, cm, 2));
                cm = fmaxf(cm, __shfl_xor_sync(0xffffffffu, cm, 1));
                float mnew = fmaxf(m, cm);
                float resc = __expf(m - mnew);
                den *= resc;
                m = mnew;
                float wsum = 0.f;
#pragma unroll
                for (int r = 0; r < 4; r++) {
                    float wr = __expf(sl[r] - m);
                    wsum += wr;
                    alpha_s[h][lane + r * 32] = wr;
                }
                wsum += __shfl_xor_sync(0xffffffffu, wsum, 16);
                wsum += __shfl_xor_sync(0xffffffffu, wsum, 8);
                wsum += __shfl_xor_sync(0xffffffffu, wsum, 4);
                wsum += __shfl_xor_sync(0xffffffffu, wsum, 2);
                wsum += __shfl_xor_sync(0xffffffffu, wsum, 1);
                den += wsum;
                if (lane == 0) resc_s[h] = resc;
            }
            __syncthreads();

            // aggregation: all 256 threads; thread (pp, quarter q), LDS-only
            {
                float rs = resc_s[h2];
                acc2 = mulx2(acc2, pkx2(rs, rs));
                int cnt4 = (cnt + 3) >> 2;
                int j0 = q * cnt4;
                int j1 = min(cnt, j0 + cnt4);
                const float* __restrict__ al = alpha_s[h2];
                const float* __restrict__ hp = hsm + 2 * pp;
                u64 a0 = 0ull, a1 = 0ull;
                int jj = j0;
                for (; jj + 2 <= j1; jj += 2) {
                    float w0 = al[jj], w1 = al[jj + 1];
                    u64 x0 = *(const u64*)(hp + srcs[jj] * HC);
                    u64 x1 = *(const u64*)(hp + srcs[jj + 1] * HC);
                    a0 = fmax2(pkx2(w0, w0), x0, a0);
                    a1 = fmax2(pkx2(w1, w1), x1, a1);
                }
                if (jj < j1) {
                    float w0 = al[jj];
                    u64 x0 = *(const u64*)(hp + srcs[jj] * HC);
                    a0 = fmax2(pkx2(w0, w0), x0, a0);
                }
                acc2 = addx2(acc2, addx2(a0, a1));
            }
            __syncthreads();
        }

        if (t < 128 && lane == 0) den_s[h] = den;
        if (q > 0) accbuf[q - 1][pp] = acc2;
        __syncthreads();
        if (q == 0) {
            u64 tot = addx2(addx2(acc2, accbuf[0][pp]),
                            addx2(accbuf[1][pp], accbuf[2][pp]));
            float2 f = upkx2(tot);
            float dd = den_s[h2] + 1e-16f;
            float v0 = f.x / dd, v1 = f.y / dd;
            float o0 = (v0 > 0.f) ? v0 : expm1f(v0);
            float o1 = (v1 > 0.f) ? v1 : expm1f(v1);
            uint32_t hi, lo;
            cvtpair(o0, o1, hi, lo);
            size_t idx = (size_t)b * (FLATd / 2) + n * (HC / 2) + pp;
            g_x_hi[idx] = hi;
            g_x_lo[idx] = lo;
        }
        __syncthreads();
    }
}

// ---------------- fc1 via mma.sync bf16 3-split (A preconverted) ----------------
#define FA_HI 0
#define FA_LO 10240
#define FB_HI 20480
#define FB_LO 25600

__global__ void __launch_bounds__(256) k_fc1_mma(const float* __restrict__ wq) {
    __shared__ __align__(16) unsigned char smbuf[30720];
    const uint32_t sb = smem_u32(smbuf);
    const int tid = threadIdx.x;
    const int wid = tid >> 5, lane = tid & 31;
    const int wm = wid & 3, wn = wid >> 2;
    const int ntile = blockIdx.x << 6;
    const int k0 = blockIdx.y << 9;

    float acc[2][4][4];
#pragma unroll
    for (int a = 0; a < 2; a++)
#pragma unroll
        for (int b = 0; b < 4; b++)
#pragma unroll
            for (int c = 0; c < 4; c++) acc[a][b][c] = 0.f;

    const uint32_t aAddrBase = sb + (uint32_t)((wm * 32 + (lane & 15)) * 80
                               + ((lane >> 4) & 1) * 16);
    const uint32_t bAddrBase = sb + (uint32_t)((wn * 32 + (lane & 7) + ((lane >> 4) ? 8 : 0)) * 80
                               + ((lane >> 3) & 1) * 16);

    const int arow = tid >> 3, asub = tid & 7;
    size_t abase = (size_t)arow * (FLATd / 2) + (k0 >> 1) + asub * 2;
    u64 hA[4], lA[4];
#pragma unroll
    for (int r = 0; r < 4; r++) {
        size_t ib = abase + (size_t)(r * 32) * (FLATd / 2);
        hA[r] = *(const u64*)(g_x_hi + ib);
        lA[r] = *(const u64*)(g_x_lo + ib);
    }
    float4 fB[2];
#pragma unroll
    for (int r = 0; r < 2; r++) {
        int i = tid + r * 256;
        fB[r] = *(const float4*)(wq + (size_t)(ntile + (i >> 3)) * FLATd + k0 + (i & 7) * 4);
    }

    for (int it = 0; it < 16; it++) {
#pragma unroll
        for (int r = 0; r < 4; r++) {
            uint32_t addr = (uint32_t)((arow + r * 32) * 80 + asub * 8);
            sts64(sb + FA_HI + addr, hA[r]);
            sts64(sb + FA_LO + addr, lA[r]);
        }
#pragma unroll
        for (int r = 0; r < 2; r++) {
            int i = tid + r * 256;
            uint32_t addr = (uint32_t)((i >> 3) * 80 + (i & 7) * 8);
            uint32_t h0, l0, h1, l1;
            cvtpair(fB[r].x, fB[r].y, h0, l0);
            cvtpair(fB[r].z, fB[r].w, h1, l1);
            sts_v2(sb + FB_HI + addr, h0, h1);
            sts_v2(sb + FB_LO + addr, l0, l1);
        }
        __syncthreads();

        if (it < 15) {
            abase += 16;
#pragma unroll
            for (int r = 0; r < 4; r++) {
                size_t ib = abase + (size_t)(r * 32) * (FLATd / 2);
                hA[r] = *(const u64*)(g_x_hi + ib);
                lA[r] = *(const u64*)(g_x_lo + ib);
            }
            int knext = k0 + (it + 1) * 32;
#pragma unroll
            for (int r = 0; r < 2; r++) {
                int i = tid + r * 256;
                fB[r] = *(const float4*)(wq + (size_t)(ntile + (i >> 3)) * FLATd + knext + (i & 7) * 4);
            }
        }

#pragma unroll
        for (int ks = 0; ks < 2; ks++) {
            uint32_t Ah[2][4], Al[2][4], Bh[2][4], Bl[2][4];
#pragma unroll
            for (int mt = 0; mt < 2; mt++) {
                uint32_t a = aAddrBase + (uint32_t)(mt * 16 * 80 + ks * 32);
                ldm_x4(Ah[mt], a + FA_HI);
                ldm_x4(Al[mt], a + FA_LO);
            }
#pragma unroll
            for (int np = 0; np < 2; np++) {
                uint32_t a = bAddrBase + (uint32_t)(np * 16 * 80 + ks * 32);
                ldm_x4(Bh[np], a + FB_HI);
                ldm_x4(Bl[np], a + FB_LO);
            }
#pragma unroll
            for (int mt = 0; mt < 2; mt++)
#pragma unroll
                for (int np = 0; np < 2; np++)
#pragma unroll
                    for (int hf = 0; hf < 2; hf++) {
                        int nt = np * 2 + hf;
                        mma_bf16(acc[mt][nt], Ah[mt], Bh[np][hf * 2], Bh[np][hf * 2 + 1]);
                        mma_bf16(acc[mt][nt], Ah[mt], Bl[np][hf * 2], Bl[np][hf * 2 + 1]);
                        mma_bf16(acc[mt][nt], Al[mt], Bh[np][hf * 2], Bh[np][hf * 2 + 1]);
                    }
        }
        __syncthreads();
    }

    float* outp = g_h1part + (size_t)blockIdx.y * (Bsz * HIDd);
#pragma unroll
    for (int mt = 0; mt < 2; mt++) {
        int rrow = wm * 32 + mt * 16 + (lane >> 2);
#pragma unroll
        for (int nt = 0; nt < 4; nt++) {
            int ccol = ntile + wn * 32 + nt * 8 + (lane & 3) * 2;
            *(float2*)&outp[(size_t)rrow * HIDd + ccol] =
                make_float2(acc[mt][nt][0], acc[mt][nt][1]);
            *(float2*)&outp[(size_t)(rrow + 8) * HIDd + ccol] =
                make_float2(acc[mt][nt][2], acc[mt][nt][3]);
        }
    }
}

// ---------------- split-K reduce + bias + BN + ReLU ----------------
__global__ void k_bnrelu(const float* __restrict__ fb,
                         const float* __restrict__ g,
                         const float* __restrict__ beta) {
    int gid = blockIdx.x * 256 + threadIdx.x;
    float s = 0.f;
#pragma unroll
    for (int p = 0; p < SPLITK; p++) s += g_h1part[(size_t)p * (Bsz * HIDd) + gid];
    int o = gid & (HIDd - 1);
    float val = (s + fb[o]) * (g[o] * rsqrtf(1.f + 1e-5f)) + beta[o];
    g_h1[gid] = fmaxf(val, 0.f);
}

// ---------------- fc2 ----------------
__global__ void k_fc2(const float* __restrict__ w2, const float* __restrict__ b2,
                      float* __restrict__ out) {
    int b = blockIdx.x, tid = threadIdx.x;
    float a0 = 0.f, a1 = 0.f;
    for (int o = tid; o < HIDd; o += 256) {
        float h = g_h1[(size_t)b * HIDd + o];
        a0 += h * w2[o];
        a1 += h * w2[HIDd + o];
    }
    __shared__ float r0[256], r1[256];
    r0[tid] = a0; r1[tid] = a1;
    __syncthreads();
    for (int s = 128; s > 0; s >>= 1) {
        if (tid < s) { r0[tid] += r0[tid + s]; r1[tid] += r1[tid + s]; }
        __syncthreads();
    }
    if (tid == 0) {
        out[b * 2 + 0] = r0[0] + b2[0];
        out[b * 2 + 1] = r1[0] + b2[1];
    }
}

extern "C" void kernel_launch(void* const* d_in, const int* in_sizes, int n_in,
                              void* d_out, int out_size) {
    const float* x       = (const float*)d_in[0];
    const int*   ei      = (const int*)  d_in[1];
    const float* eattr   = (const float*)d_in[2];
    const float* tcn_w   = (const float*)d_in[3];
    const float* tcn_b   = (const float*)d_in[4];
    const float* lin_l_w = (const float*)d_in[5];
    const float* lin_l_b = (const float*)d_in[6];
    const float* lin_e_w = (const float*)d_in[7];
    const float* lin_e_b = (const float*)d_in[8];
    const float* att     = (const float*)d_in[9];
    const float* fc1_w   = (const float*)d_in[10];
    const float* fc1_b   = (const float*)d_in[11];
    const float* bn_g    = (const float*)d_in[12];
    const float* bn_b    = (const float*)d_in[13];
    const float* fc2_w   = (const float*)d_in[14];
    const float* fc2_b   = (const float*)d_in[15];
    float* out = (float*)d_out;

    k_csr<<<1, 512>>>(ei);
    k_tcn<<<dim3(4, Bsz), 128>>>(x, tcn_w, tcn_b);
    k_linl<<<dim3(2, Bsz), 256>>>(lin_l_w, lin_l_b);
    k_score<<<dim3(EE / 64, Bsz), 256>>>(ei, eattr, lin_e_w, lin_e_b, att);
    k_agg<<<dim3(NN / NPB, Bsz), 256>>>();
    k_fc1_mma<<<dim3(32, SPLITK), 256>>>(fc1_w);
    k_bnrelu<<<(Bsz * HIDd) / 256, 256>>>(fc1_b, bn_g, bn_b);
    k_fc2<<<Bsz, 256>>>(fc2_w, fc2_b, out);
}

// round 14
// speedup vs baseline: 1.0983x; 1.0983x over previous
#include <cuda_runtime.h>
#include <cuda_bf16.h>
#include <math.h>
#include <stdint.h>

#define Bsz   128
#define Wd    128
#define FIN   64
#define NN    64
#define EE    4096
#define EDd   16
#define HC    128
#define FLATd 8192
#define HIDd  2048
#define SPLITK 16
#define EVW   132

// ---------------- scratch ----------------
__device__ __align__(128) float g_xg[Bsz * NN * Wd];
__device__ __align__(128) float g_h[Bsz * NN * HC];
__device__ __align__(128) float g_xflat[Bsz * FLATd];
__device__ __align__(128) float g_h1part[SPLITK * Bsz * HIDd];
__device__ __align__(128) float g_score[Bsz * EE * 4];   // [b][e][h]
__device__ int  g_csr_off[NN + 1];
__device__ int2 g_csr_es[EE];

// ---------------- helpers ----------------
__device__ __forceinline__ uint32_t smem_u32(const void* p) {
    uint32_t a;
    asm("{ .reg .u64 t; cvta.to.shared.u64 t, %1; cvt.u32.u64 %0, t; }" : "=r"(a) : "l"(p));
    return a;
}
__device__ __forceinline__ void ldm_x4(uint32_t (&r)[4], uint32_t addr) {
    asm volatile("ldmatrix.sync.aligned.m8n8.x4.shared.b16 {%0,%1,%2,%3}, [%4];"
        : "=r"(r[0]), "=r"(r[1]), "=r"(r[2]), "=r"(r[3]) : "r"(addr));
}
__device__ __forceinline__ void mma_bf16(float (&d)[4], const uint32_t (&a)[4],
                                         uint32_t b0, uint32_t b1) {
    asm volatile(
        "mma.sync.aligned.m16n8k16.row.col.f32.bf16.bf16.f32 "
        "{%0,%1,%2,%3}, {%4,%5,%6,%7}, {%8,%9}, {%0,%1,%2,%3};"
        : "+f"(d[0]), "+f"(d[1]), "+f"(d[2]), "+f"(d[3])
        : "r"(a[0]), "r"(a[1]), "r"(a[2]), "r"(a[3]), "r"(b0), "r"(b1));
}
__device__ __forceinline__ void cvtpair(float a, float b, uint32_t& hi, uint32_t& lo) {
    __nv_bfloat16 ha = __float2bfloat16(a), hb2 = __float2bfloat16(b);
    float ra = a - __bfloat162float(ha), rb = b - __bfloat162float(hb2);
    __nv_bfloat16 la = __float2bfloat16(ra), lb = __float2bfloat16(rb);
    hi = (uint32_t)__bfloat16_as_ushort(ha) | ((uint32_t)__bfloat16_as_ushort(hb2) << 16);
    lo = (uint32_t)__bfloat16_as_ushort(la) | ((uint32_t)__bfloat16_as_ushort(lb) << 16);
}
__device__ __forceinline__ void sts_v2(uint32_t addr, uint32_t x, uint32_t y) {
    asm volatile("st.shared.v2.b32 [%0], {%1,%2};" :: "r"(addr), "r"(x), "r"(y) : "memory");
}
typedef unsigned long long u64;
__device__ __forceinline__ u64 pkx2(float lo, float hi) {
    u64 r; asm("mov.b64 %0, {%1,%2};" : "=l"(r) : "f"(lo), "f"(hi)); return r;
}
__device__ __forceinline__ u64 addx2(u64 a, u64 b) {
    u64 d; asm("add.rn.f32x2 %0, %1, %2;" : "=l"(d) : "l"(a), "l"(b)); return d;
}
__device__ __forceinline__ u64 mulx2(u64 a, u64 b) {
    u64 d; asm("mul.rn.f32x2 %0, %1, %2;" : "=l"(d) : "l"(a), "l"(b)); return d;
}
__device__ __forceinline__ u64 fmax2(u64 a, u64 b, u64 c) {
    u64 d; asm("fma.rn.f32x2 %0, %1, %2, %3;" : "=l"(d) : "l"(a), "l"(b), "l"(c)); return d;
}

// ---------------- CSR build ----------------
__global__ void k_csr(const int* __restrict__ ei) {
    __shared__ int cnt[NN];
    __shared__ int off[NN + 1];
    __shared__ int cur[NN];
    int tid = threadIdx.x;
    if (tid < NN) cnt[tid] = 0;
    __syncthreads();
    for (int e = tid; e < EE; e += blockDim.x)
        atomicAdd(&cnt[ei[EE + e]], 1);
    __syncthreads();
    if (tid == 0) {
        int run = 0;
        for (int k = 0; k < NN; k++) { off[k] = run; cur[k] = run; run += cnt[k]; }
        off[NN] = run;
    }
    __syncthreads();
    for (int e = tid; e < EE; e += blockDim.x) {
        int d = ei[EE + e];
        int pos = atomicAdd(&cur[d], 1);
        g_csr_es[pos] = make_int2(e, ei[e]);
    }
    if (tid <= NN) g_csr_off[tid] = off[tid];
}

// ---------------- TCN conv1d(k=3,pad=1) ----------------
__global__ void k_tcn(const float* __restrict__ x,
                      const float* __restrict__ tw,
                      const float* __restrict__ tb) {
    __shared__ float xs[FIN * 129];
    __shared__ float sw[16 * 192];
    int b = blockIdx.y, nc = blockIdx.x;
    int tid = threadIdx.x;
    const float* xb = x + (size_t)b * Wd * FIN;
    for (int idx = tid; idx < Wd * FIN; idx += 128) {
        int w = idx >> 6, i = idx & 63;
        xs[i * 129 + w] = xb[idx];
    }
    for (int idx = tid; idx < 16 * 192; idx += 128)
        sw[idx] = tw[nc * 16 * 192 + idx];
    __syncthreads();
    int w = tid;
    float acc[16];
#pragma unroll
    for (int nl = 0; nl < 16; nl++) acc[nl] = tb[nc * 16 + nl];
    for (int i = 0; i < FIN; i++) {
        float x0 = xs[i * 129 + w];
        float xm = (w > 0)   ? xs[i * 129 + w - 1] : 0.f;
        float xp = (w < 127) ? xs[i * 129 + w + 1] : 0.f;
#pragma unroll
        for (int nl = 0; nl < 16; nl++) {
            const float* wp = &sw[nl * 192 + i * 3];
            acc[nl] += xm * wp[0] + x0 * wp[1] + xp * wp[2];
        }
    }
#pragma unroll
    for (int nl = 0; nl < 16; nl++)
        g_xg[((size_t)b * NN + nc * 16 + nl) * Wd + w] = acc[nl];
}

// ---------------- lin_l projection ----------------
__global__ void k_linl(const float* __restrict__ lw, const float* __restrict__ lb) {
    __shared__ float xs[NN * 129];
    __shared__ float ws[64 * 33];
    int b = blockIdx.y, oc = blockIdx.x;
    int tid = threadIdx.x;
    for (int idx = tid; idx < NN * Wd; idx += 256) {
        int n = idx >> 7, w = idx & 127;
        xs[n * 129 + w] = g_xg[(size_t)b * NN * Wd + idx];
    }
    int tx = tid & 15, ty = tid >> 4;
    float acc[4][4];
#pragma unroll
    for (int i = 0; i < 4; i++)
#pragma unroll
        for (int j = 0; j < 4; j++) acc[i][j] = 0.f;
    for (int wc = 0; wc < 4; wc++) {
        __syncthreads();
        for (int idx = tid; idx < 64 * 32; idx += 256) {
            int ol = idx >> 5, wl = idx & 31;
            ws[ol * 33 + wl] = lw[(oc * 64 + ol) * Wd + wc * 32 + wl];
        }
        __syncthreads();
#pragma unroll 4
        for (int wl = 0; wl < 32; wl++) {
            float a[4], bb[4];
#pragma unroll
            for (int j = 0; j < 4; j++) a[j]  = xs[(ty * 4 + j) * 129 + wc * 32 + wl];
#pragma unroll
            for (int j = 0; j < 4; j++) bb[j] = ws[(tx * 4 + j) * 33 + wl];
#pragma unroll
            for (int i = 0; i < 4; i++)
#pragma unroll
                for (int j = 0; j < 4; j++) acc[i][j] += a[i] * bb[j];
        }
    }
#pragma unroll
    for (int i = 0; i < 4; i++)
#pragma unroll
        for (int j = 0; j < 4; j++) {
            int n = ty * 4 + i, o = oc * 64 + tx * 4 + j;
            g_h[((size_t)b * NN + n) * HC + o] = acc[i][j] + lb[o];
        }
}

// ---------------- k_score: 2x64-edge tiles/block, pipelined prefetch ----------------
__global__ void __launch_bounds__(256, 5) k_score(const int* __restrict__ ei,
                       const float* __restrict__ eattr,
                       const float* __restrict__ lew,
                       const float* __restrict__ leb,
                       const float* __restrict__ att) {
    __shared__ uint32_t bfrag[2][2][4][2][32];       // [hi/lo][eh][nt][reg][lane]
    __shared__ __align__(16) float ev_s[64 * EVW];
    __shared__ int src_s[64], dst_s[64];

    int e0 = blockIdx.x << 7, b = blockIdx.y;
    int t = threadIdx.x, lane = t & 31, w = t >> 5;
    int wq = w & 1, wc = w >> 1;
    int g = lane >> 2, tq = lane & 3;

    // A fragments: channel group wc (32 channels), bf16 hi/lo
    uint32_t Ah[2][4], Al[2][4];
#pragma unroll
    for (int mt = 0; mt < 2; mt++) {
        int ch0 = wc * 32 + mt * 16 + g;
        const float* wr0 = lew + ch0 * EDd;
        const float* wr1 = lew + (ch0 + 8) * EDd;
        float2 p0 = *(const float2*)(wr0 + 2 * tq);
        float2 p1 = *(const float2*)(wr1 + 2 * tq);
        float2 p2 = *(const float2*)(wr0 + 2 * tq + 8);
        float2 p3 = *(const float2*)(wr1 + 2 * tq + 8);
        cvtpair(p0.x, p0.y, Ah[mt][0], Al[mt][0]);
        cvtpair(p1.x, p1.y, Ah[mt][1], Al[mt][1]);
        cvtpair(p2.x, p2.y, Ah[mt][2], Al[mt][2]);
        cvtpair(p3.x, p3.y, Ah[mt][3], Al[mt][3]);
    }

    // epilogue constants
    int pp = t & 63, g4 = t >> 6;
    const float* hb = g_h + (size_t)b * NN * HC;
    u64 att2 = *(const u64*)(att + 2 * pp);
    u64 eb2  = *(const u64*)(leb + 2 * pp);
    u64 aC1 = mulx2(att2, pkx2(0.505f, 0.505f));
    u64 aC2 = mulx2(att2, pkx2(0.495f, 0.495f));
    const u64 MSK = 0x7FFFFFFF7FFFFFFFull;

    // prefetch tile 0
    int j = t >> 2, q = t & 3;
    float4 pf_ea = *(const float4*)(eattr + (size_t)b * EE * EDd
                                    + (size_t)(e0 + j) * EDd + q * 4);
    int pf_src = 0, pf_dst = 0;
    if (t < 64) {
        pf_src = ei[e0 + t];
        pf_dst = ei[EE + e0 + t];
    }

    for (int eT = 0; eT < 2; eT++) {
        int eb = e0 + eT * 64;
        // stage prefetched data
        if (t < 64) { src_s[t] = pf_src; dst_s[t] = pf_dst; }
        {
            uint32_t h0, l0, h1, l1;
            cvtpair(pf_ea.x, pf_ea.y, h0, l0);
            cvtpair(pf_ea.z, pf_ea.w, h1, l1);
            int eh = j >> 5, j32 = j & 31;
            int nt = j32 >> 3, reg = q >> 1;
            int lpos = (j32 & 7) * 4 + (q & 1) * 2;
            bfrag[0][eh][nt][reg][lpos] = h0; bfrag[0][eh][nt][reg][lpos + 1] = h1;
            bfrag[1][eh][nt][reg][lpos] = l0; bfrag[1][eh][nt][reg][lpos + 1] = l1;
        }
        __syncthreads();

        // issue prefetch for next tile (overlaps mma + epilogue below)
        if (eT == 0) {
            int en = e0 + 64;
            pf_ea = *(const float4*)(eattr + (size_t)b * EE * EDd
                                     + (size_t)(en + j) * EDd + q * 4);
            if (t < 64) {
                pf_src = ei[en + t];
                pf_dst = ei[EE + en + t];
            }
        }

        // mma: warp (wq, wc): its 32 channels for its 32 edges (3-term bf16 split)
#pragma unroll
        for (int nt = 0; nt < 4; nt++) {
            uint32_t b0h = bfrag[0][wq][nt][0][lane], b1h = bfrag[0][wq][nt][1][lane];
            uint32_t b0l = bfrag[1][wq][nt][0][lane], b1l = bfrag[1][wq][nt][1][lane];
#pragma unroll
            for (int mt = 0; mt < 2; mt++) {
                float a4[4] = {0.f, 0.f, 0.f, 0.f};
                mma_bf16(a4, Ah[mt], b0h, b1h);
                mma_bf16(a4, Ah[mt], b0l, b1l);
                mma_bf16(a4, Al[mt], b0h, b1h);
                int ch = wc * 32 + mt * 16 + g;
                int el = wq * 32 + nt * 8 + 2 * tq;
                ev_s[el * EVW + ch]           = a4[0];
                ev_s[(el + 1) * EVW + ch]     = a4[1];
                ev_s[el * EVW + ch + 8]       = a4[2];
                ev_s[(el + 1) * EVW + ch + 8] = a4[3];
            }
        }
        __syncthreads();

        // epilogue: f32x2 over channel pairs
#pragma unroll 4
        for (int r = 0; r < 16; r++) {
            int e = g4 * 16 + r;
            int s = src_s[e], d = dst_s[e];
            u64 hs2 = *(const u64*)(hb + s * HC + 2 * pp);
            u64 hd2 = *(const u64*)(hb + d * HC + 2 * pp);
            u64 ev2 = *(const u64*)&ev_s[e * EVW + 2 * pp];
            u64 z = addx2(addx2(hs2, hd2), addx2(ev2, eb2));
            u64 az; asm("and.b64 %0, %1, %2;" : "=l"(az) : "l"(z), "l"(MSK));
            *(u64*)&ev_s[e * EVW + 2 * pp] = fmax2(az, aC2, mulx2(z, aC1));
        }
        __syncthreads();

        // reduce: thread (e = t&63, h = t>>6) sums 32 channels -> score
        {
            int e = t & 63, h = t >> 6;
            const float* rp = &ev_s[e * EVW + h * 32];
            float s0 = 0.f, s1 = 0.f, s2 = 0.f, s3 = 0.f;
#pragma unroll
            for (int c4 = 0; c4 < 8; c4++) {
                float4 v = *(const float4*)(rp + c4 * 4);
                s0 += v.x; s1 += v.y; s2 += v.z; s3 += v.w;
            }
            g_score[((size_t)b * EE + eb + e) * 4 + h] = (s0 + s1) + (s2 + s3);
        }
        if (eT == 0) __syncthreads();   // before overwriting bfrag/src_s
    }
}

// ---------------- k_agg: per-node softmax + aggregation (R10 version) ----------------
__global__ void __launch_bounds__(128) k_agg() {
    __shared__ int2   es_s[128];
    __shared__ float4 sc_s[128];
    __shared__ float  alpha_s[4][128];
    int n = blockIdx.x, b = blockIdx.y;
    int t = threadIdx.x, lane = t & 31, h = t >> 5;
    const float* __restrict__ hb = g_h + (size_t)b * NN * HC;
    const float* __restrict__ hbt = hb + t;

    int beg = g_csr_off[n], end = g_csr_off[n + 1];
    int deg = end - beg;
    const int2* lst = g_csr_es + beg;

    float m = -1e30f, den = 0.f, acc = 0.f;

    for (int base = 0; base < deg; base += 128) {
        int cnt = min(128, deg - base);
        if (t < cnt) {
            int2 p = lst[base + t];
            es_s[t] = p;
            sc_s[t] = *(const float4*)&g_score[((size_t)b * EE + p.x) * 4];
        }
        __syncthreads();

        float sl[4];
#pragma unroll
        for (int r = 0; r < 4; r++) {
            int jj = lane + r * 32;
            sl[r] = (jj < cnt) ? ((const float*)&sc_s[jj])[h] : -1e30f;
        }
        float cm = fmaxf(fmaxf(sl[0], sl[1]), fmaxf(sl[2], sl[3]));
        cm = fmaxf(cm, __shfl_xor_sync(0xffffffffu, cm, 16));
        cm = fmaxf(cm, __shfl_xor_sync(0xffffffffu, cm, 8));
        cm = fmaxf(cm, __shfl_xor_sync(0xffffffffu, cm, 4));
        cm = fmaxf(cm, __shfl_xor_sync(0xffffffffu, cm, 2));
        cm = fmaxf(cm, __shfl_xor_sync(0xffffffffu, cm, 1));
        float mnew = fmaxf(m, cm);
        float resc = __expf(m - mnew);
        den *= resc; acc *= resc;
        m = mnew;
        float wsum = 0.f;
#pragma unroll
        for (int r = 0; r < 4; r++) {
            float wr = __expf(sl[r] - m);
            wsum += wr;
            alpha_s[h][lane + r * 32] = wr;
        }
        wsum += __shfl_xor_sync(0xffffffffu, wsum, 16);
        wsum += __shfl_xor_sync(0xffffffffu, wsum, 8);
        wsum += __shfl_xor_sync(0xffffffffu, wsum, 4);
        wsum += __shfl_xor_sync(0xffffffffu, wsum, 2);
        wsum += __shfl_xor_sync(0xffffffffu, wsum, 1);
        den += wsum;
        __syncwarp();

        const float* __restrict__ al = alpha_s[h];
        float a0 = 0.f, a1 = 0.f, a2 = 0.f, a3 = 0.f;
        int jj = 0;
        for (; jj + 4 <= cnt; jj += 4) {
            a0 += al[jj]     * hbt[es_s[jj].y * HC];
            a1 += al[jj + 1] * hbt[es_s[jj + 1].y * HC];
            a2 += al[jj + 2] * hbt[es_s[jj + 2].y * HC];
            a3 += al[jj + 3] * hbt[es_s[jj + 3].y * HC];
        }
        for (; jj < cnt; jj++)
            a0 += al[jj] * hbt[es_s[jj].y * HC];
        acc += (a0 + a1) + (a2 + a3);
        __syncthreads();
    }

    float v = acc / (den + 1e-16f);
    float o = (v > 0.f) ? v : expm1f(v);
    g_xflat[(size_t)b * FLATd + n * HC + t] = o;
}

// ---------------- fc1 via mma.sync bf16 3-split ----------------
#define FA_HI 0
#define FA_LO 10240
#define FB_HI 20480
#define FB_LO 25600

__global__ void __launch_bounds__(256) k_fc1_mma(const float* __restrict__ wq) {
    __shared__ __align__(16) unsigned char smbuf[30720];
    const uint32_t sb = smem_u32(smbuf);
    const int tid = threadIdx.x;
    const int wid = tid >> 5, lane = tid & 31;
    const int wm = wid & 3, wn = wid >> 2;
    const int ntile = blockIdx.x << 6;
    const int k0 = blockIdx.y << 9;

    float acc[2][4][4];
#pragma unroll
    for (int a = 0; a < 2; a++)
#pragma unroll
        for (int b = 0; b < 4; b++)
#pragma unroll
            for (int c = 0; c < 4; c++) acc[a][b][c] = 0.f;

    const uint32_t aAddrBase = sb + (uint32_t)((wm * 32 + (lane & 15)) * 80
                               + ((lane >> 4) & 1) * 16);
    const uint32_t bAddrBase = sb + (uint32_t)((wn * 32 + (lane & 7) + ((lane >> 4) ? 8 : 0)) * 80
                               + ((lane >> 3) & 1) * 16);

    float4 fA[4], fB[2];
#pragma unroll
    for (int r = 0; r < 4; r++) {
        int i = tid + r * 256;
        fA[r] = *(const float4*)(g_xflat + (size_t)(i >> 3) * FLATd + k0 + (i & 7) * 4);
    }
#pragma unroll
    for (int r = 0; r < 2; r++) {
        int i = tid + r * 256;
        fB[r] = *(const float4*)(wq + (size_t)(ntile + (i >> 3)) * FLATd + k0 + (i & 7) * 4);
    }

    for (int it = 0; it < 16; it++) {
#pragma unroll
        for (int r = 0; r < 4; r++) {
            int i = tid + r * 256;
            uint32_t addr = (uint32_t)((i >> 3) * 80 + (i & 7) * 8);
            uint32_t h0, l0, h1, l1;
            cvtpair(fA[r].x, fA[r].y, h0, l0);
            cvtpair(fA[r].z, fA[r].w, h1, l1);
            sts_v2(sb + FA_HI + addr, h0, h1);
            sts_v2(sb + FA_LO + addr, l0, l1);
        }
#pragma unroll
        for (int r = 0; r < 2; r++) {
            int i = tid + r * 256;
            uint32_t addr = (uint32_t)((i >> 3) * 80 + (i & 7) * 8);
            uint32_t h0, l0, h1, l1;
            cvtpair(fB[r].x, fB[r].y, h0, l0);
            cvtpair(fB[r].z, fB[r].w, h1, l1);
            sts_v2(sb + FB_HI + addr, h0, h1);
            sts_v2(sb + FB_LO + addr, l0, l1);
        }
        __syncthreads();

        if (it < 15) {
            int knext = k0 + (it + 1) * 32;
#pragma unroll
            for (int r = 0; r < 4; r++) {
                int i = tid + r * 256;
                fA[r] = *(const float4*)(g_xflat + (size_t)(i >> 3) * FLATd + knext + (i & 7) * 4);
            }
#pragma unroll
            for (int r = 0; r < 2; r++) {
                int i = tid + r * 256;
                fB[r] = *(const float4*)(wq + (size_t)(ntile + (i >> 3)) * FLATd + knext + (i & 7) * 4);
            }
        }

#pragma unroll
        for (int ks = 0; ks < 2; ks++) {
            uint32_t Ah[2][4], Al[2][4], Bh[2][4], Bl[2][4];
#pragma unroll
            for (int mt = 0; mt < 2; mt++) {
                uint32_t a = aAddrBase + (uint32_t)(mt * 16 * 80 + ks * 32);
                ldm_x4(Ah[mt], a + FA_HI);
                ldm_x4(Al[mt], a + FA_LO);
            }
#pragma unroll
            for (int np = 0; np < 2; np++) {
                uint32_t a = bAddrBase + (uint32_t)(np * 16 * 80 + ks * 32);
                ldm_x4(Bh[np], a + FB_HI);
                ldm_x4(Bl[np], a + FB_LO);
            }
#pragma unroll
            for (int mt = 0; mt < 2; mt++)
#pragma unroll
                for (int np = 0; np < 2; np++)
#pragma unroll
                    for (int hf = 0; hf < 2; hf++) {
                        int nt = np * 2 + hf;
                        mma_bf16(acc[mt][nt], Ah[mt], Bh[np][hf * 2], Bh[np][hf * 2 + 1]);
                        mma_bf16(acc[mt][nt], Ah[mt], Bl[np][hf * 2], Bl[np][hf * 2 + 1]);
                        mma_bf16(acc[mt][nt], Al[mt], Bh[np][hf * 2], Bh[np][hf * 2 + 1]);
                    }
        }
        __syncthreads();
    }

    float* outp = g_h1part + (size_t)blockIdx.y * (Bsz * HIDd);
#pragma unroll
    for (int mt = 0; mt < 2; mt++) {
        int rrow = wm * 32 + mt * 16 + (lane >> 2);
#pragma unroll
        for (int nt = 0; nt < 4; nt++) {
            int ccol = ntile + wn * 32 + nt * 8 + (lane & 3) * 2;
            *(float2*)&outp[(size_t)rrow * HIDd + ccol] =
                make_float2(acc[mt][nt][0], acc[mt][nt][1]);
            *(float2*)&outp[(size_t)(rrow + 8) * HIDd + ccol] =
                make_float2(acc[mt][nt][2], acc[mt][nt][3]);
        }
    }
}

// ---------------- fused: split-K reduce + bias + BN + ReLU + fc2 ----------------
__global__ void k_fc2f(const float* __restrict__ fb,
                       const float* __restrict__ bng,
                       const float* __restrict__ bnb,
                       const float* __restrict__ w2,
                       const float* __restrict__ b2,
                       float* __restrict__ out) {
    int b = blockIdx.x, tid = threadIdx.x;
    const float bns = rsqrtf(1.f + 1e-5f);
    float a0 = 0.f, a1 = 0.f;
    for (int o = tid; o < HIDd; o += 256) {
        float s = 0.f;
#pragma unroll
        for (int p = 0; p < SPLITK; p++)
            s += g_h1part[(size_t)p * (Bsz * HIDd) + (size_t)b * HIDd + o];
        float val = (s + fb[o]) * (bng[o] * bns) + bnb[o];
        val = fmaxf(val, 0.f);
        a0 += val * w2[o];
        a1 += val * w2[HIDd + o];
    }
    __shared__ float r0[256], r1[256];
    r0[tid] = a0; r1[tid] = a1;
    __syncthreads();
    for (int s = 128; s > 0; s >>= 1) {
        if (tid < s) { r0[tid] += r0[tid + s]; r1[tid] += r1[tid + s]; }
        __syncthreads();
    }
    if (tid == 0) {
        out[b * 2 + 0] = r0[0] + b2[0];
        out[b * 2 + 1] = r1[0] + b2[1];
    }
}

extern "C" void kernel_launch(void* const* d_in, const int* in_sizes, int n_in,
                              void* d_out, int out_size) {
    const float* x       = (const float*)d_in[0];
    const int*   ei      = (const int*)  d_in[1];
    const float* eattr   = (const float*)d_in[2];
    const float* tcn_w   = (const float*)d_in[3];
    const float* tcn_b   = (const float*)d_in[4];
    const float* lin_l_w = (const float*)d_in[5];
    const float* lin_l_b = (const float*)d_in[6];
    const float* lin_e_w = (const float*)d_in[7];
    const float* lin_e_b = (const float*)d_in[8];
    const float* att     = (const float*)d_in[9];
    const float* fc1_w   = (const float*)d_in[10];
    const float* fc1_b   = (const float*)d_in[11];
    const float* bn_g    = (const float*)d_in[12];
    const float* bn_b    = (const float*)d_in[13];
    const float* fc2_w   = (const float*)d_in[14];
    const float* fc2_b   = (const float*)d_in[15];
    float* out = (float*)d_out;

    k_csr<<<1, 512>>>(ei);
    k_tcn<<<dim3(4, Bsz), 128>>>(x, tcn_w, tcn_b);
    k_linl<<<dim3(2, Bsz), 256>>>(lin_l_w, lin_l_b);
    k_score<<<dim3(EE / 128, Bsz), 256>>>(ei, eattr, lin_e_w, lin_e_b, att);
    k_agg<<<dim3(NN, Bsz), 128>>>();
    k_fc1_mma<<<dim3(32, SPLITK), 256>>>(fc1_w);
    k_fc2f<<<Bsz, 256>>>(fc1_b, bn_g, bn_b, fc2_w, fc2_b, out);
}

// round 15
// speedup vs baseline: 1.1680x; 1.0634x over previous
#include <cuda_runtime.h>
#include <cuda_bf16.h>
#include <math.h>
#include <stdint.h>

#define Bsz   128
#define Wd    128
#define FIN   64
#define NN    64
#define EE    4096
#define EDd   16
#define HC    128
#define FLATd 8192
#define HIDd  2048
#define SPLITK 16
#define EVW   132

// fused tcn+linl smem layout (floats)
#define SW_OFF 0            // 64*192 = 12288
#define XS_OFF 12288        // 64*132 = 8448 (padded cols 0 and 130)
#define XG_OFF 20736        // 64*130 = 8320
#define WS_OFF 29056        // 64*33  = 2112
#define TL_SMEM ((29056 + 2112) * 4)   // 124672 B

// ---------------- scratch ----------------
__device__ __align__(128) float g_h[Bsz * NN * HC];
__device__ __align__(128) float g_xflat[Bsz * FLATd];
__device__ __align__(128) float g_h1part[SPLITK * Bsz * HIDd];
__device__ __align__(128) float g_score[Bsz * EE * 4];
__device__ int  g_csr_off[NN + 1];
__device__ int2 g_csr_es[EE];

// ---------------- helpers ----------------
__device__ __forceinline__ uint32_t smem_u32(const void* p) {
    uint32_t a;
    asm("{ .reg .u64 t; cvta.to.shared.u64 t, %1; cvt.u32.u64 %0, t; }" : "=r"(a) : "l"(p));
    return a;
}
__device__ __forceinline__ void ldm_x4(uint32_t (&r)[4], uint32_t addr) {
    asm volatile("ldmatrix.sync.aligned.m8n8.x4.shared.b16 {%0,%1,%2,%3}, [%4];"
        : "=r"(r[0]), "=r"(r[1]), "=r"(r[2]), "=r"(r[3]) : "r"(addr));
}
__device__ __forceinline__ void mma_bf16(float (&d)[4], const uint32_t (&a)[4],
                                         uint32_t b0, uint32_t b1) {
    asm volatile(
        "mma.sync.aligned.m16n8k16.row.col.f32.bf16.bf16.f32 "
        "{%0,%1,%2,%3}, {%4,%5,%6,%7}, {%8,%9}, {%0,%1,%2,%3};"
        : "+f"(d[0]), "+f"(d[1]), "+f"(d[2]), "+f"(d[3])
        : "r"(a[0]), "r"(a[1]), "r"(a[2]), "r"(a[3]), "r"(b0), "r"(b1));
}
__device__ __forceinline__ void cvtpair(float a, float b, uint32_t& hi, uint32_t& lo) {
    __nv_bfloat16 ha = __float2bfloat16(a), hb2 = __float2bfloat16(b);
    float ra = a - __bfloat162float(ha), rb = b - __bfloat162float(hb2);
    __nv_bfloat16 la = __float2bfloat16(ra), lb = __float2bfloat16(rb);
    hi = (uint32_t)__bfloat16_as_ushort(ha) | ((uint32_t)__bfloat16_as_ushort(hb2) << 16);
    lo = (uint32_t)__bfloat16_as_ushort(la) | ((uint32_t)__bfloat16_as_ushort(lb) << 16);
}
__device__ __forceinline__ void sts_v2(uint32_t addr, uint32_t x, uint32_t y) {
    asm volatile("st.shared.v2.b32 [%0], {%1,%2};" :: "r"(addr), "r"(x), "r"(y) : "memory");
}
typedef unsigned long long u64;
__device__ __forceinline__ u64 pkx2(float lo, float hi) {
    u64 r; asm("mov.b64 %0, {%1,%2};" : "=l"(r) : "f"(lo), "f"(hi)); return r;
}
__device__ __forceinline__ u64 addx2(u64 a, u64 b) {
    u64 d; asm("add.rn.f32x2 %0, %1, %2;" : "=l"(d) : "l"(a), "l"(b)); return d;
}
__device__ __forceinline__ u64 mulx2(u64 a, u64 b) {
    u64 d; asm("mul.rn.f32x2 %0, %1, %2;" : "=l"(d) : "l"(a), "l"(b)); return d;
}
__device__ __forceinline__ u64 fmax2(u64 a, u64 b, u64 c) {
    u64 d; asm("fma.rn.f32x2 %0, %1, %2, %3;" : "=l"(d) : "l"(a), "l"(b), "l"(c)); return d;
}
__device__ __forceinline__ float2 upkx2(u64 v) {
    float2 r; asm("mov.b64 {%0,%1}, %2;" : "=f"(r.x), "=f"(r.y) : "l"(v)); return r;
}

// ---------------- CSR build ----------------
__global__ void k_csr(const int* __restrict__ ei) {
    __shared__ int cnt[NN];
    __shared__ int off[NN + 1];
    __shared__ int cur[NN];
    int tid = threadIdx.x;
    if (tid < NN) cnt[tid] = 0;
    __syncthreads();
    for (int e = tid; e < EE; e += blockDim.x)
        atomicAdd(&cnt[ei[EE + e]], 1);
    __syncthreads();
    if (tid == 0) {
        int run = 0;
        for (int k = 0; k < NN; k++) { off[k] = run; cur[k] = run; run += cnt[k]; }
        off[NN] = run;
    }
    __syncthreads();
    for (int e = tid; e < EE; e += blockDim.x) {
        int d = ei[EE + e];
        int pos = atomicAdd(&cur[d], 1);
        g_csr_es[pos] = make_int2(e, ei[e]);
    }
    if (tid <= NN) g_csr_off[tid] = off[tid];
}

// ---------------- fused TCN conv1d + lin_l (one wave, 128 blocks) ----------------
__global__ void __launch_bounds__(256) k_tcnlinl(const float* __restrict__ x,
                        const float* __restrict__ tw,
                        const float* __restrict__ tb,
                        const float* __restrict__ lw,
                        const float* __restrict__ lb) {
    extern __shared__ float sm[];
    float* sw = sm + SW_OFF;
    float* xs = sm + XS_OFF;   // [i][w+1], pitch 132, cols 0 & 130 zero
    float* xg = sm + XG_OFF;   // [n][w], pitch 130
    float* ws = sm + WS_OFF;   // [ol][wl], pitch 33

    int b = blockIdx.x, t = threadIdx.x;
    const float* xb = x + (size_t)b * Wd * FIN;

    for (int i = t; i < NN * 192; i += 256) sw[i] = tw[i];
    for (int idx = t; idx < Wd * FIN; idx += 256) {
        int w = idx >> 6, i = idx & 63;
        xs[i * 132 + w + 1] = xb[idx];
    }
    if (t < 128) {
        int i = t & 63;
        xs[i * 132 + ((t >> 6) ? 129 : 0)] = 0.f;
    }
    __syncthreads();

    // ---- phase 1: conv, f32x2 over w pairs; thread = (wp, ng of 16 channels) ----
    {
        int wp = t & 63, ng = t >> 6;
        u64 acc[16];
#pragma unroll
        for (int c = 0; c < 16; c++) {
            float bv = tb[ng * 16 + c];
            acc[c] = pkx2(bv, bv);
        }
        for (int i = 0; i < FIN; i++) {
            const float* xr = xs + i * 132 + 2 * wp;
            u64 m2 = *(const u64*)xr;          // (x[w0-1], x[w1-1])
            u64 p2 = *(const u64*)(xr + 2);    // (x[w0+1], x[w1+1])
            float2 am = upkx2(m2), ap = upkx2(p2);
            u64 x0 = pkx2(am.y, ap.x);         // (x[w0], x[w1])
            const float* swi = sw + i * 3;
#pragma unroll
            for (int c = 0; c < 16; c++) {
                const float* wv = swi + (ng * 16 + c) * 192;
                float w0 = wv[0], w1 = wv[1], w2 = wv[2];
                acc[c] = fmax2(m2, pkx2(w0, w0), acc[c]);
                acc[c] = fmax2(x0, pkx2(w1, w1), acc[c]);
                acc[c] = fmax2(p2, pkx2(w2, w2), acc[c]);
            }
        }
#pragma unroll
        for (int c = 0; c < 16; c++)
            *(u64*)&xg[(ng * 16 + c) * 130 + 2 * wp] = acc[c];
    }

    // ---- phase 2: lin_l from smem xg ----
    int tx = t & 15, ty = t >> 4;
    for (int oc = 0; oc < 2; oc++) {
        float acc[4][4];
#pragma unroll
        for (int i = 0; i < 4; i++)
#pragma unroll
            for (int j = 0; j < 4; j++) acc[i][j] = 0.f;
        for (int wc = 0; wc < 4; wc++) {
            __syncthreads();
            for (int idx = t; idx < 64 * 32; idx += 256) {
                int ol = idx >> 5, wl = idx & 31;
                ws[ol * 33 + wl] = lw[(oc * 64 + ol) * Wd + wc * 32 + wl];
            }
            __syncthreads();
#pragma unroll 4
            for (int wl = 0; wl < 32; wl++) {
                float a[4], bb[4];
#pragma unroll
                for (int j = 0; j < 4; j++) a[j]  = xg[(ty * 4 + j) * 130 + wc * 32 + wl];
#pragma unroll
                for (int j = 0; j < 4; j++) bb[j] = ws[(tx * 4 + j) * 33 + wl];
#pragma unroll
                for (int i = 0; i < 4; i++)
#pragma unroll
                    for (int j = 0; j < 4; j++) acc[i][j] += a[i] * bb[j];
            }
        }
#pragma unroll
        for (int i = 0; i < 4; i++)
#pragma unroll
            for (int j = 0; j < 4; j++) {
                int n = ty * 4 + i, o = oc * 64 + tx * 4 + j;
                g_h[((size_t)b * NN + n) * HC + o] = acc[i][j] + lb[o];
            }
    }
}

// ---------------- k_score: 4x64-edge tiles/block, pipelined prefetch ----------------
__global__ void __launch_bounds__(256, 5) k_score(const int* __restrict__ ei,
                       const float* __restrict__ eattr,
                       const float* __restrict__ lew,
                       const float* __restrict__ leb,
                       const float* __restrict__ att) {
    __shared__ uint32_t bfrag[2][2][4][2][32];
    __shared__ __align__(16) float ev_s[64 * EVW];
    __shared__ int src_s[64], dst_s[64];

    int e0 = blockIdx.x << 8, b = blockIdx.y;
    int t = threadIdx.x, lane = t & 31, w = t >> 5;
    int wq = w & 1, wc = w >> 1;
    int g = lane >> 2, tq = lane & 3;

    uint32_t Ah[2][4], Al[2][4];
#pragma unroll
    for (int mt = 0; mt < 2; mt++) {
        int ch0 = wc * 32 + mt * 16 + g;
        const float* wr0 = lew + ch0 * EDd;
        const float* wr1 = lew + (ch0 + 8) * EDd;
        float2 p0 = *(const float2*)(wr0 + 2 * tq);
        float2 p1 = *(const float2*)(wr1 + 2 * tq);
        float2 p2 = *(const float2*)(wr0 + 2 * tq + 8);
        float2 p3 = *(const float2*)(wr1 + 2 * tq + 8);
        cvtpair(p0.x, p0.y, Ah[mt][0], Al[mt][0]);
        cvtpair(p1.x, p1.y, Ah[mt][1], Al[mt][1]);
        cvtpair(p2.x, p2.y, Ah[mt][2], Al[mt][2]);
        cvtpair(p3.x, p3.y, Ah[mt][3], Al[mt][3]);
    }

    int pp = t & 63, g4 = t >> 6;
    const float* hb = g_h + (size_t)b * NN * HC;
    u64 att2 = *(const u64*)(att + 2 * pp);
    u64 eb2  = *(const u64*)(leb + 2 * pp);
    u64 aC1 = mulx2(att2, pkx2(0.505f, 0.505f));
    u64 aC2 = mulx2(att2, pkx2(0.495f, 0.495f));
    const u64 MSK = 0x7FFFFFFF7FFFFFFFull;

    int j = t >> 2, q = t & 3;
    float4 pf_ea = *(const float4*)(eattr + (size_t)b * EE * EDd
                                    + (size_t)(e0 + j) * EDd + q * 4);
    int pf_src = 0, pf_dst = 0;
    if (t < 64) {
        pf_src = ei[e0 + t];
        pf_dst = ei[EE + e0 + t];
    }

    for (int eT = 0; eT < 4; eT++) {
        int eb = e0 + eT * 64;
        if (t < 64) { src_s[t] = pf_src; dst_s[t] = pf_dst; }
        {
            uint32_t h0, l0, h1, l1;
            cvtpair(pf_ea.x, pf_ea.y, h0, l0);
            cvtpair(pf_ea.z, pf_ea.w, h1, l1);
            int eh = j >> 5, j32 = j & 31;
            int nt = j32 >> 3, reg = q >> 1;
            int lpos = (j32 & 7) * 4 + (q & 1) * 2;
            bfrag[0][eh][nt][reg][lpos] = h0; bfrag[0][eh][nt][reg][lpos + 1] = h1;
            bfrag[1][eh][nt][reg][lpos] = l0; bfrag[1][eh][nt][reg][lpos + 1] = l1;
        }
        __syncthreads();

        if (eT < 3) {
            int en = e0 + (eT + 1) * 64;
            pf_ea = *(const float4*)(eattr + (size_t)b * EE * EDd
                                     + (size_t)(en + j) * EDd + q * 4);
            if (t < 64) {
                pf_src = ei[en + t];
                pf_dst = ei[EE + en + t];
            }
        }

#pragma unroll
        for (int nt = 0; nt < 4; nt++) {
            uint32_t b0h = bfrag[0][wq][nt][0][lane], b1h = bfrag[0][wq][nt][1][lane];
            uint32_t b0l = bfrag[1][wq][nt][0][lane], b1l = bfrag[1][wq][nt][1][lane];
#pragma unroll
            for (int mt = 0; mt < 2; mt++) {
                float a4[4] = {0.f, 0.f, 0.f, 0.f};
                mma_bf16(a4, Ah[mt], b0h, b1h);
                mma_bf16(a4, Ah[mt], b0l, b1l);
                mma_bf16(a4, Al[mt], b0h, b1h);
                int ch = wc * 32 + mt * 16 + g;
                int el = wq * 32 + nt * 8 + 2 * tq;
                ev_s[el * EVW + ch]           = a4[0];
                ev_s[(el + 1) * EVW + ch]     = a4[1];
                ev_s[el * EVW + ch + 8]       = a4[2];
                ev_s[(el + 1) * EVW + ch + 8] = a4[3];
            }
        }
        __syncthreads();

#pragma unroll 4
        for (int r = 0; r < 16; r++) {
            int e = g4 * 16 + r;
            int s = src_s[e], d = dst_s[e];
            u64 hs2 = *(const u64*)(hb + s * HC + 2 * pp);
            u64 hd2 = *(const u64*)(hb + d * HC + 2 * pp);
            u64 ev2 = *(const u64*)&ev_s[e * EVW + 2 * pp];
            u64 z = addx2(addx2(hs2, hd2), addx2(ev2, eb2));
            u64 az; asm("and.b64 %0, %1, %2;" : "=l"(az) : "l"(z), "l"(MSK));
            *(u64*)&ev_s[e * EVW + 2 * pp] = fmax2(az, aC2, mulx2(z, aC1));
        }
        __syncthreads();

        {
            int e = t & 63, h = t >> 6;
            const float* rp = &ev_s[e * EVW + h * 32];
            float s0 = 0.f, s1 = 0.f, s2 = 0.f, s3 = 0.f;
#pragma unroll
            for (int c4 = 0; c4 < 8; c4++) {
                float4 v = *(const float4*)(rp + c4 * 4);
                s0 += v.x; s1 += v.y; s2 += v.z; s3 += v.w;
            }
            g_score[((size_t)b * EE + eb + e) * 4 + h] = (s0 + s1) + (s2 + s3);
        }
        if (eT < 3) __syncthreads();
    }
}

// ---------------- k_agg (R10/R14 version) ----------------
__global__ void __launch_bounds__(128) k_agg() {
    __shared__ int2   es_s[128];
    __shared__ float4 sc_s[128];
    __shared__ float  alpha_s[4][128];
    int n = blockIdx.x, b = blockIdx.y;
    int t = threadIdx.x, lane = t & 31, h = t >> 5;
    const float* __restrict__ hb = g_h + (size_t)b * NN * HC;
    const float* __restrict__ hbt = hb + t;

    int beg = g_csr_off[n], end = g_csr_off[n + 1];
    int deg = end - beg;
    const int2* lst = g_csr_es + beg;

    float m = -1e30f, den = 0.f, acc = 0.f;

    for (int base = 0; base < deg; base += 128) {
        int cnt = min(128, deg - base);
        if (t < cnt) {
            int2 p = lst[base + t];
            es_s[t] = p;
            sc_s[t] = *(const float4*)&g_score[((size_t)b * EE + p.x) * 4];
        }
        __syncthreads();

        float sl[4];
#pragma unroll
        for (int r = 0; r < 4; r++) {
            int jj = lane + r * 32;
            sl[r] = (jj < cnt) ? ((const float*)&sc_s[jj])[h] : -1e30f;
        }
        float cm = fmaxf(fmaxf(sl[0], sl[1]), fmaxf(sl[2], sl[3]));
        cm = fmaxf(cm, __shfl_xor_sync(0xffffffffu, cm, 16));
        cm = fmaxf(cm, __shfl_xor_sync(0xffffffffu, cm, 8));
        cm = fmaxf(cm, __shfl_xor_sync(0xffffffffu, cm, 4));
        cm = fmaxf(cm, __shfl_xor_sync(0xffffffffu, cm, 2));
        cm = fmaxf(cm, __shfl_xor_sync(0xffffffffu, cm, 1));
        float mnew = fmaxf(m, cm);
        float resc = __expf(m - mnew);
        den *= resc; acc *= resc;
        m = mnew;
        float wsum = 0.f;
#pragma unroll
        for (int r = 0; r < 4; r++) {
            float wr = __expf(sl[r] - m);
            wsum += wr;
            alpha_s[h][lane + r * 32] = wr;
        }
        wsum += __shfl_xor_sync(0xffffffffu, wsum, 16);
        wsum += __shfl_xor_sync(0xffffffffu, wsum, 8);
        wsum += __shfl_xor_sync(0xffffffffu, wsum, 4);
        wsum += __shfl_xor_sync(0xffffffffu, wsum, 2);
        wsum += __shfl_xor_sync(0xffffffffu, wsum, 1);
        den += wsum;
        __syncwarp();

        const float* __restrict__ al = alpha_s[h];
        float a0 = 0.f, a1 = 0.f, a2 = 0.f, a3 = 0.f;
        int jj = 0;
        for (; jj + 4 <= cnt; jj += 4) {
            a0 += al[jj]     * hbt[es_s[jj].y * HC];
            a1 += al[jj + 1] * hbt[es_s[jj + 1].y * HC];
            a2 += al[jj + 2] * hbt[es_s[jj + 2].y * HC];
            a3 += al[jj + 3] * hbt[es_s[jj + 3].y * HC];
        }
        for (; jj < cnt; jj++)
            a0 += al[jj] * hbt[es_s[jj].y * HC];
        acc += (a0 + a1) + (a2 + a3);
        __syncthreads();
    }

    float v = acc / (den + 1e-16f);
    float o = (v > 0.f) ? v : expm1f(v);
    g_xflat[(size_t)b * FLATd + n * HC + t] = o;
}

// ---------------- fc1 via mma.sync bf16 3-split ----------------
#define FA_HI 0
#define FA_LO 10240
#define FB_HI 20480
#define FB_LO 25600

__global__ void __launch_bounds__(256) k_fc1_mma(const float* __restrict__ wq) {
    __shared__ __align__(16) unsigned char smbuf[30720];
    const uint32_t sb = smem_u32(smbuf);
    const int tid = threadIdx.x;
    const int wid = tid >> 5, lane = tid & 31;
    const int wm = wid & 3, wn = wid >> 2;
    const int ntile = blockIdx.x << 6;
    const int k0 = blockIdx.y << 9;

    float acc[2][4][4];
#pragma unroll
    for (int a = 0; a < 2; a++)
#pragma unroll
        for (int b = 0; b < 4; b++)
#pragma unroll
            for (int c = 0; c < 4; c++) acc[a][b][c] = 0.f;

    const uint32_t aAddrBase = sb + (uint32_t)((wm * 32 + (lane & 15)) * 80
                               + ((lane >> 4) & 1) * 16);
    const uint32_t bAddrBase = sb + (uint32_t)((wn * 32 + (lane & 7) + ((lane >> 4) ? 8 : 0)) * 80
                               + ((lane >> 3) & 1) * 16);

    float4 fA[4], fB[2];
#pragma unroll
    for (int r = 0; r < 4; r++) {
        int i = tid + r * 256;
        fA[r] = *(const float4*)(g_xflat + (size_t)(i >> 3) * FLATd + k0 + (i & 7) * 4);
    }
#pragma unroll
    for (int r = 0; r < 2; r++) {
        int i = tid + r * 256;
        fB[r] = *(const float4*)(wq + (size_t)(ntile + (i >> 3)) * FLATd + k0 + (i & 7) * 4);
    }

    for (int it = 0; it < 16; it++) {
#pragma unroll
        for (int r = 0; r < 4; r++) {
            int i = tid + r * 256;
            uint32_t addr = (uint32_t)((i >> 3) * 80 + (i & 7) * 8);
            uint32_t h0, l0, h1, l1;
            cvtpair(fA[r].x, fA[r].y, h0, l0);
            cvtpair(fA[r].z, fA[r].w, h1, l1);
            sts_v2(sb + FA_HI + addr, h0, h1);
            sts_v2(sb + FA_LO + addr, l0, l1);
        }
#pragma unroll
        for (int r = 0; r < 2; r++) {
            int i = tid + r * 256;
            uint32_t addr = (uint32_t)((i >> 3) * 80 + (i & 7) * 8);
            uint32_t h0, l0, h1, l1;
            cvtpair(fB[r].x, fB[r].y, h0, l0);
            cvtpair(fB[r].z, fB[r].w, h1, l1);
            sts_v2(sb + FB_HI + addr, h0, h1);
            sts_v2(sb + FB_LO + addr, l0, l1);
        }
        __syncthreads();

        if (it < 15) {
            int knext = k0 + (it + 1) * 32;
#pragma unroll
            for (int r = 0; r < 4; r++) {
                int i = tid + r * 256;
                fA[r] = *(const float4*)(g_xflat + (size_t)(i >> 3) * FLATd + knext + (i & 7) * 4);
            }
#pragma unroll
            for (int r = 0; r < 2; r++) {
                int i = tid + r * 256;
                fB[r] = *(const float4*)(wq + (size_t)(ntile + (i >> 3)) * FLATd + knext + (i & 7) * 4);
            }
        }

#pragma unroll
        for (int ks = 0; ks < 2; ks++) {
            uint32_t Ah[2][4], Al[2][4], Bh[2][4], Bl[2][4];
#pragma unroll
            for (int mt = 0; mt < 2; mt++) {
                uint32_t a = aAddrBase + (uint32_t)(mt * 16 * 80 + ks * 32);
                ldm_x4(Ah[mt], a + FA_HI);
                ldm_x4(Al[mt], a + FA_LO);
            }
#pragma unroll
            for (int np = 0; np < 2; np++) {
                uint32_t a = bAddrBase + (uint32_t)(np * 16 * 80 + ks * 32);
                ldm_x4(Bh[np], a + FB_HI);
                ldm_x4(Bl[np], a + FB_LO);
            }
#pragma unroll
            for (int mt = 0; mt < 2; mt++)
#pragma unroll
                for (int np = 0; np < 2; np++)
#pragma unroll
                    for (int hf = 0; hf < 2; hf++) {
                        int nt = np * 2 + hf;
                        mma_bf16(acc[mt][nt], Ah[mt], Bh[np][hf * 2], Bh[np][hf * 2 + 1]);
                        mma_bf16(acc[mt][nt], Ah[mt], Bl[np][hf * 2], Bl[np][hf * 2 + 1]);
                        mma_bf16(acc[mt][nt], Al[mt], Bh[np][hf * 2], Bh[np][hf * 2 + 1]);
                    }
        }
        __syncthreads();
    }

    float* outp = g_h1part + (size_t)blockIdx.y * (Bsz * HIDd);
#pragma unroll
    for (int mt = 0; mt < 2; mt++) {
        int rrow = wm * 32 + mt * 16 + (lane >> 2);
#pragma unroll
        for (int nt = 0; nt < 4; nt++) {
            int ccol = ntile + wn * 32 + nt * 8 + (lane & 3) * 2;
            *(float2*)&outp[(size_t)rrow * HIDd + ccol] =
                make_float2(acc[mt][nt][0], acc[mt][nt][1]);
            *(float2*)&outp[(size_t)(rrow + 8) * HIDd + ccol] =
                make_float2(acc[mt][nt][2], acc[mt][nt][3]);
        }
    }
}

// ---------------- fused: split-K reduce + bias + BN + ReLU + fc2 ----------------
__global__ void k_fc2f(const float* __restrict__ fb,
                       const float* __restrict__ bng,
                       const float* __restrict__ bnb,
                       const float* __restrict__ w2,
                       const float* __restrict__ b2,
                       float* __restrict__ out) {
    int b = blockIdx.x, tid = threadIdx.x;
    const float bns = rsqrtf(1.f + 1e-5f);
    float a0 = 0.f, a1 = 0.f;
    for (int o = tid; o < HIDd; o += 256) {
        float s = 0.f;
#pragma unroll
        for (int p = 0; p < SPLITK; p++)
            s += g_h1part[(size_t)p * (Bsz * HIDd) + (size_t)b * HIDd + o];
        float val = (s + fb[o]) * (bng[o] * bns) + bnb[o];
        val = fmaxf(val, 0.f);
        a0 += val * w2[o];
        a1 += val * w2[HIDd + o];
    }
    __shared__ float r0[256], r1[256];
    r0[tid] = a0; r1[tid] = a1;
    __syncthreads();
    for (int s = 128; s > 0; s >>= 1) {
        if (tid < s) { r0[tid] += r0[tid + s]; r1[tid] += r1[tid + s]; }
        __syncthreads();
    }
    if (tid == 0) {
        out[b * 2 + 0] = r0[0] + b2[0];
        out[b * 2 + 1] = r1[0] + b2[1];
    }
}

extern "C" void kernel_launch(void* const* d_in, const int* in_sizes, int n_in,
                              void* d_out, int out_size) {
    const float* x       = (const float*)d_in[0];
    const int*   ei      = (const int*)  d_in[1];
    const float* eattr   = (const float*)d_in[2];
    const float* tcn_w   = (const float*)d_in[3];
    const float* tcn_b   = (const float*)d_in[4];
    const float* lin_l_w = (const float*)d_in[5];
    const float* lin_l_b = (const float*)d_in[6];
    const float* lin_e_w = (const float*)d_in[7];
    const float* lin_e_b = (const float*)d_in[8];
    const float* att     = (const float*)d_in[9];
    const float* fc1_w   = (const float*)d_in[10];
    const float* fc1_b   = (const float*)d_in[11];
    const float* bn_g    = (const float*)d_in[12];
    const float* bn_b    = (const float*)d_in[13];
    const float* fc2_w   = (const float*)d_in[14];
    const float* fc2_b   = (const float*)d_in[15];
    float* out = (float*)d_out;

    cudaFuncSetAttribute(k_tcnlinl, cudaFuncAttributeMaxDynamicSharedMemorySize, TL_SMEM);

    k_csr<<<1, 512>>>(ei);
    k_tcnlinl<<<Bsz, 256, TL_SMEM>>>(x, tcn_w, tcn_b, lin_l_w, lin_l_b);
    k_score<<<dim3(EE / 256, Bsz), 256>>>(ei, eattr, lin_e_w, lin_e_b, att);
    k_agg<<<dim3(NN, Bsz), 128>>>();
    k_fc1_mma<<<dim3(32, SPLITK), 256>>>(fc1_w);
    k_fc2f<<<Bsz, 256>>>(fc1_b, bn_g, bn_b, fc2_w, fc2_b, out);
}

// round 16
// speedup vs baseline: 1.1804x; 1.0107x over previous
#include <cuda_runtime.h>
#include <cuda_bf16.h>
#include <math.h>
#include <stdint.h>

#define Bsz   128
#define Wd    128
#define FIN   64
#define NN    64
#define EE    4096
#define EDd   16
#define HC    128
#define FLATd 8192
#define HIDd  2048
#define SPLITK 16
#define EVW   132

// fused tcn+linl smem layout (floats)
#define SW_OFF 0            // 64*192 = 12288
#define XS_OFF 12288        // 64*132 = 8448
#define XG_OFF 20736        // 64*130 = 8320
#define WS_OFF 29056        // 64*33  = 2112
#define TL_SMEM ((29056 + 2112) * 4)   // 124672 B

// ---------------- scratch ----------------
__device__ __align__(128) float g_h[Bsz * NN * HC];
__device__ __align__(128) uint32_t g_x_hi[Bsz * (FLATd / 2)];
__device__ __align__(128) uint32_t g_x_lo[Bsz * (FLATd / 2)];
__device__ __align__(128) float g_h1part[SPLITK * Bsz * HIDd];
__device__ __align__(128) float g_score[Bsz * EE * 4];
__device__ int  g_csr_off[NN + 1];
__device__ int2 g_csr_es[EE];

// ---------------- helpers ----------------
__device__ __forceinline__ uint32_t smem_u32(const void* p) {
    uint32_t a;
    asm("{ .reg .u64 t; cvta.to.shared.u64 t, %1; cvt.u32.u64 %0, t; }" : "=r"(a) : "l"(p));
    return a;
}
__device__ __forceinline__ void ldm_x4(uint32_t (&r)[4], uint32_t addr) {
    asm volatile("ldmatrix.sync.aligned.m8n8.x4.shared.b16 {%0,%1,%2,%3}, [%4];"
        : "=r"(r[0]), "=r"(r[1]), "=r"(r[2]), "=r"(r[3]) : "r"(addr));
}
__device__ __forceinline__ void mma_bf16(float (&d)[4], const uint32_t (&a)[4],
                                         uint32_t b0, uint32_t b1) {
    asm volatile(
        "mma.sync.aligned.m16n8k16.row.col.f32.bf16.bf16.f32 "
        "{%0,%1,%2,%3}, {%4,%5,%6,%7}, {%8,%9}, {%0,%1,%2,%3};"
        : "+f"(d[0]), "+f"(d[1]), "+f"(d[2]), "+f"(d[3])
        : "r"(a[0]), "r"(a[1]), "r"(a[2]), "r"(a[3]), "r"(b0), "r"(b1));
}
__device__ __forceinline__ void cvtpair(float a, float b, uint32_t& hi, uint32_t& lo) {
    __nv_bfloat16 ha = __float2bfloat16(a), hb2 = __float2bfloat16(b);
    float ra = a - __bfloat162float(ha), rb = b - __bfloat162float(hb2);
    __nv_bfloat16 la = __float2bfloat16(ra), lb = __float2bfloat16(rb);
    hi = (uint32_t)__bfloat16_as_ushort(ha) | ((uint32_t)__bfloat16_as_ushort(hb2) << 16);
    lo = (uint32_t)__bfloat16_as_ushort(la) | ((uint32_t)__bfloat16_as_ushort(lb) << 16);
}
__device__ __forceinline__ void sts_v2(uint32_t addr, uint32_t x, uint32_t y) {
    asm volatile("st.shared.v2.b32 [%0], {%1,%2};" :: "r"(addr), "r"(x), "r"(y) : "memory");
}
typedef unsigned long long u64;
__device__ __forceinline__ void sts64(uint32_t addr, u64 v) {
    asm volatile("st.shared.b64 [%0], %1;" :: "r"(addr), "l"(v) : "memory");
}
__device__ __forceinline__ u64 pkx2(float lo, float hi) {
    u64 r; asm("mov.b64 %0, {%1,%2};" : "=l"(r) : "f"(lo), "f"(hi)); return r;
}
__device__ __forceinline__ u64 addx2(u64 a, u64 b) {
    u64 d; asm("add.rn.f32x2 %0, %1, %2;" : "=l"(d) : "l"(a), "l"(b)); return d;
}
__device__ __forceinline__ u64 mulx2(u64 a, u64 b) {
    u64 d; asm("mul.rn.f32x2 %0, %1, %2;" : "=l"(d) : "l"(a), "l"(b)); return d;
}
__device__ __forceinline__ u64 fmax2(u64 a, u64 b, u64 c) {
    u64 d; asm("fma.rn.f32x2 %0, %1, %2, %3;" : "=l"(d) : "l"(a), "l"(b), "l"(c)); return d;
}
__device__ __forceinline__ float2 upkx2(u64 v) {
    float2 r; asm("mov.b64 {%0,%1}, %2;" : "=f"(r.x), "=f"(r.y) : "l"(v)); return r;
}

// ---------------- fused: TCN conv1d + lin_l (blocks 0-127) | CSR build (block 128) ----------------
__global__ void __launch_bounds__(256) k_tcnlinl(const float* __restrict__ x,
                        const float* __restrict__ tw,
                        const float* __restrict__ tb,
                        const float* __restrict__ lw,
                        const float* __restrict__ lb,
                        const int* __restrict__ ei) {
    extern __shared__ float sm[];
    int t = threadIdx.x;

    if (blockIdx.x == Bsz) {
        // ---- CSR build role ----
        int* cnt = (int*)sm;            // NN
        int* off = cnt + NN;            // NN+1
        int* cur = off + NN + 1;        // NN
        if (t < NN) cnt[t] = 0;
        __syncthreads();
        for (int e = t; e < EE; e += 256)
            atomicAdd(&cnt[ei[EE + e]], 1);
        __syncthreads();
        if (t == 0) {
            int run = 0;
            for (int k = 0; k < NN; k++) { off[k] = run; cur[k] = run; run += cnt[k]; }
            off[NN] = run;
        }
        __syncthreads();
        for (int e = t; e < EE; e += 256) {
            int d = ei[EE + e];
            int pos = atomicAdd(&cur[d], 1);
            g_csr_es[pos] = make_int2(e, ei[e]);
        }
        if (t <= NN) g_csr_off[t] = off[t];
        return;
    }

    float* sw = sm + SW_OFF;
    float* xs = sm + XS_OFF;
    float* xg = sm + XG_OFF;
    float* ws = sm + WS_OFF;

    int b = blockIdx.x;
    const float* xb = x + (size_t)b * Wd * FIN;

    for (int i = t; i < NN * 192; i += 256) sw[i] = tw[i];
    for (int idx = t; idx < Wd * FIN; idx += 256) {
        int w = idx >> 6, i = idx & 63;
        xs[i * 132 + w + 1] = xb[idx];
    }
    if (t < 128) {
        int i = t & 63;
        xs[i * 132 + ((t >> 6) ? 129 : 0)] = 0.f;
    }
    __syncthreads();

    // phase 1: conv, f32x2 over w pairs
    {
        int wp = t & 63, ng = t >> 6;
        u64 acc[16];
#pragma unroll
        for (int c = 0; c < 16; c++) {
            float bv = tb[ng * 16 + c];
            acc[c] = pkx2(bv, bv);
        }
        for (int i = 0; i < FIN; i++) {
            const float* xr = xs + i * 132 + 2 * wp;
            u64 m2 = *(const u64*)xr;
            u64 p2 = *(const u64*)(xr + 2);
            float2 am = upkx2(m2), ap = upkx2(p2);
            u64 x0 = pkx2(am.y, ap.x);
            const float* swi = sw + i * 3;
#pragma unroll
            for (int c = 0; c < 16; c++) {
                const float* wv = swi + (ng * 16 + c) * 192;
                float w0 = wv[0], w1 = wv[1], w2 = wv[2];
                acc[c] = fmax2(m2, pkx2(w0, w0), acc[c]);
                acc[c] = fmax2(x0, pkx2(w1, w1), acc[c]);
                acc[c] = fmax2(p2, pkx2(w2, w2), acc[c]);
            }
        }
#pragma unroll
        for (int c = 0; c < 16; c++)
            *(u64*)&xg[(ng * 16 + c) * 130 + 2 * wp] = acc[c];
    }

    // phase 2: lin_l from smem xg
    int tx = t & 15, ty = t >> 4;
    for (int oc = 0; oc < 2; oc++) {
        float acc[4][4];
#pragma unroll
        for (int i = 0; i < 4; i++)
#pragma unroll
            for (int j = 0; j < 4; j++) acc[i][j] = 0.f;
        for (int wc = 0; wc < 4; wc++) {
            __syncthreads();
            for (int idx = t; idx < 64 * 32; idx += 256) {
                int ol = idx >> 5, wl = idx & 31;
                ws[ol * 33 + wl] = lw[(oc * 64 + ol) * Wd + wc * 32 + wl];
            }
            __syncthreads();
#pragma unroll 4
            for (int wl = 0; wl < 32; wl++) {
                float a[4], bb[4];
#pragma unroll
                for (int j = 0; j < 4; j++) a[j]  = xg[(ty * 4 + j) * 130 + wc * 32 + wl];
#pragma unroll
                for (int j = 0; j < 4; j++) bb[j] = ws[(tx * 4 + j) * 33 + wl];
#pragma unroll
                for (int i = 0; i < 4; i++)
#pragma unroll
                    for (int j = 0; j < 4; j++) acc[i][j] += a[i] * bb[j];
            }
        }
#pragma unroll
        for (int i = 0; i < 4; i++)
#pragma unroll
            for (int j = 0; j < 4; j++) {
                int n = ty * 4 + i, o = oc * 64 + tx * 4 + j;
                g_h[((size_t)b * NN + n) * HC + o] = acc[i][j] + lb[o];
            }
    }
}

// ---------------- k_score: 4x64-edge tiles/block, pipelined prefetch ----------------
__global__ void __launch_bounds__(256, 5) k_score(const int* __restrict__ ei,
                       const float* __restrict__ eattr,
                       const float* __restrict__ lew,
                       const float* __restrict__ leb,
                       const float* __restrict__ att) {
    __shared__ uint32_t bfrag[2][2][4][2][32];
    __shared__ __align__(16) float ev_s[64 * EVW];
    __shared__ int src_s[64], dst_s[64];

    int e0 = blockIdx.x << 8, b = blockIdx.y;
    int t = threadIdx.x, lane = t & 31, w = t >> 5;
    int wq = w & 1, wc = w >> 1;
    int g = lane >> 2, tq = lane & 3;

    uint32_t Ah[2][4], Al[2][4];
#pragma unroll
    for (int mt = 0; mt < 2; mt++) {
        int ch0 = wc * 32 + mt * 16 + g;
        const float* wr0 = lew + ch0 * EDd;
        const float* wr1 = lew + (ch0 + 8) * EDd;
        float2 p0 = *(const float2*)(wr0 + 2 * tq);
        float2 p1 = *(const float2*)(wr1 + 2 * tq);
        float2 p2 = *(const float2*)(wr0 + 2 * tq + 8);
        float2 p3 = *(const float2*)(wr1 + 2 * tq + 8);
        cvtpair(p0.x, p0.y, Ah[mt][0], Al[mt][0]);
        cvtpair(p1.x, p1.y, Ah[mt][1], Al[mt][1]);
        cvtpair(p2.x, p2.y, Ah[mt][2], Al[mt][2]);
        cvtpair(p3.x, p3.y, Ah[mt][3], Al[mt][3]);
    }

    int pp = t & 63, g4 = t >> 6;
    const float* hb = g_h + (size_t)b * NN * HC;
    u64 att2 = *(const u64*)(att + 2 * pp);
    u64 eb2  = *(const u64*)(leb + 2 * pp);
    u64 aC1 = mulx2(att2, pkx2(0.505f, 0.505f));
    u64 aC2 = mulx2(att2, pkx2(0.495f, 0.495f));
    const u64 MSK = 0x7FFFFFFF7FFFFFFFull;

    int j = t >> 2, q = t & 3;
    float4 pf_ea = *(const float4*)(eattr + (size_t)b * EE * EDd
                                    + (size_t)(e0 + j) * EDd + q * 4);
    int pf_src = 0, pf_dst = 0;
    if (t < 64) {
        pf_src = ei[e0 + t];
        pf_dst = ei[EE + e0 + t];
    }

    for (int eT = 0; eT < 4; eT++) {
        int eb = e0 + eT * 64;
        if (t < 64) { src_s[t] = pf_src; dst_s[t] = pf_dst; }
        {
            uint32_t h0, l0, h1, l1;
            cvtpair(pf_ea.x, pf_ea.y, h0, l0);
            cvtpair(pf_ea.z, pf_ea.w, h1, l1);
            int eh = j >> 5, j32 = j & 31;
            int nt = j32 >> 3, reg = q >> 1;
            int lpos = (j32 & 7) * 4 + (q & 1) * 2;
            bfrag[0][eh][nt][reg][lpos] = h0; bfrag[0][eh][nt][reg][lpos + 1] = h1;
            bfrag[1][eh][nt][reg][lpos] = l0; bfrag[1][eh][nt][reg][lpos + 1] = l1;
        }
        __syncthreads();

        if (eT < 3) {
            int en = e0 + (eT + 1) * 64;
            pf_ea = *(const float4*)(eattr + (size_t)b * EE * EDd
                                     + (size_t)(en + j) * EDd + q * 4);
            if (t < 64) {
                pf_src = ei[en + t];
                pf_dst = ei[EE + en + t];
            }
        }

#pragma unroll
        for (int nt = 0; nt < 4; nt++) {
            uint32_t b0h = bfrag[0][wq][nt][0][lane], b1h = bfrag[0][wq][nt][1][lane];
            uint32_t b0l = bfrag[1][wq][nt][0][lane], b1l = bfrag[1][wq][nt][1][lane];
#pragma unroll
            for (int mt = 0; mt < 2; mt++) {
                float a4[4] = {0.f, 0.f, 0.f, 0.f};
                mma_bf16(a4, Ah[mt], b0h, b1h);
                mma_bf16(a4, Ah[mt], b0l, b1l);
                mma_bf16(a4, Al[mt], b0h, b1h);
                int ch = wc * 32 + mt * 16 + g;
                int el = wq * 32 + nt * 8 + 2 * tq;
                ev_s[el * EVW + ch]           = a4[0];
                ev_s[(el + 1) * EVW + ch]     = a4[1];
                ev_s[el * EVW + ch + 8]       = a4[2];
                ev_s[(el + 1) * EVW + ch + 8] = a4[3];
            }
        }
        __syncthreads();

#pragma unroll 4
        for (int r = 0; r < 16; r++) {
            int e = g4 * 16 + r;
            int s = src_s[e], d = dst_s[e];
            u64 hs2 = *(const u64*)(hb + s * HC + 2 * pp);
            u64 hd2 = *(const u64*)(hb + d * HC + 2 * pp);
            u64 ev2 = *(const u64*)&ev_s[e * EVW + 2 * pp];
            u64 z = addx2(addx2(hs2, hd2), addx2(ev2, eb2));
            u64 az; asm("and.b64 %0, %1, %2;" : "=l"(az) : "l"(z), "l"(MSK));
            *(u64*)&ev_s[e * EVW + 2 * pp] = fmax2(az, aC2, mulx2(z, aC1));
        }
        __syncthreads();

        {
            int e = t & 63, h = t >> 6;
            const float* rp = &ev_s[e * EVW + h * 32];
            float s0 = 0.f, s1 = 0.f, s2 = 0.f, s3 = 0.f;
#pragma unroll
            for (int c4 = 0; c4 < 8; c4++) {
                float4 v = *(const float4*)(rp + c4 * 4);
                s0 += v.x; s1 += v.y; s2 += v.z; s3 += v.w;
            }
            g_score[((size_t)b * EE + eb + e) * 4 + h] = (s0 + s1) + (s2 + s3);
        }
        if (eT < 3) __syncthreads();
    }
}

// ---------------- k_agg: softmax + aggregation, emits bf16 hi/lo A ----------------
__global__ void __launch_bounds__(128) k_agg() {
    __shared__ int2   es_s[128];
    __shared__ float4 sc_s[128];
    __shared__ float  alpha_s[4][128];
    int n = blockIdx.x, b = blockIdx.y;
    int t = threadIdx.x, lane = t & 31, h = t >> 5;
    const float* __restrict__ hb = g_h + (size_t)b * NN * HC;
    const float* __restrict__ hbt = hb + t;

    int beg = g_csr_off[n], end = g_csr_off[n + 1];
    int deg = end - beg;
    const int2* lst = g_csr_es + beg;

    float m = -1e30f, den = 0.f, acc = 0.f;

    for (int base = 0; base < deg; base += 128) {
        int cnt = min(128, deg - base);
        if (t < cnt) {
            int2 p = lst[base + t];
            es_s[t] = p;
            sc_s[t] = *(const float4*)&g_score[((size_t)b * EE + p.x) * 4];
        }
        __syncthreads();

        float sl[4];
#pragma unroll
        for (int r = 0; r < 4; r++) {
            int jj = lane + r * 32;
            sl[r] = (jj < cnt) ? ((const float*)&sc_s[jj])[h] : -1e30f;
        }
        float cm = fmaxf(fmaxf(sl[0], sl[1]), fmaxf(sl[2], sl[3]));
        cm = fmaxf(cm, __shfl_xor_sync(0xffffffffu, cm, 16));
        cm = fmaxf(cm, __shfl_xor_sync(0xffffffffu, cm, 8));
        cm = fmaxf(cm, __shfl_xor_sync(0xffffffffu, cm, 4));
        cm = fmaxf(cm, __shfl_xor_sync(0xffffffffu, cm, 2));
        cm = fmaxf(cm, __shfl_xor_sync(0xffffffffu, cm, 1));
        float mnew = fmaxf(m, cm);
        float resc = __expf(m - mnew);
        den *= resc; acc *= resc;
        m = mnew;
        float wsum = 0.f;
#pragma unroll
        for (int r = 0; r < 4; r++) {
            float wr = __expf(sl[r] - m);
            wsum += wr;
            alpha_s[h][lane + r * 32] = wr;
        }
        wsum += __shfl_xor_sync(0xffffffffu, wsum, 16);
        wsum += __shfl_xor_sync(0xffffffffu, wsum, 8);
        wsum += __shfl_xor_sync(0xffffffffu, wsum, 4);
        wsum += __shfl_xor_sync(0xffffffffu, wsum, 2);
        wsum += __shfl_xor_sync(0xffffffffu, wsum, 1);
        den += wsum;
        __syncwarp();

        const float* __restrict__ al = alpha_s[h];
        float a0 = 0.f, a1 = 0.f, a2 = 0.f, a3 = 0.f;
        int jj = 0;
        for (; jj + 4 <= cnt; jj += 4) {
            a0 += al[jj]     * hbt[es_s[jj].y * HC];
            a1 += al[jj + 1] * hbt[es_s[jj + 1].y * HC];
            a2 += al[jj + 2] * hbt[es_s[jj + 2].y * HC];
            a3 += al[jj + 3] * hbt[es_s[jj + 3].y * HC];
        }
        for (; jj < cnt; jj++)
            a0 += al[jj] * hbt[es_s[jj].y * HC];
        acc += (a0 + a1) + (a2 + a3);
        __syncthreads();
    }

    float v = acc / (den + 1e-16f);
    float o = (v > 0.f) ? v : expm1f(v);
    float o2 = __shfl_xor_sync(0xffffffffu, o, 1);   // partner channel
    if (!(t & 1)) {
        uint32_t hi, lo;
        cvtpair(o, o2, hi, lo);
        size_t idx = (size_t)b * (FLATd / 2) + n * (HC / 2) + (t >> 1);
        g_x_hi[idx] = hi;
        g_x_lo[idx] = lo;
    }
}

// ---------------- fc1 via mma.sync bf16 3-split (A preconverted) ----------------
#define FA_HI 0
#define FA_LO 10240
#define FB_HI 20480
#define FB_LO 25600

__global__ void __launch_bounds__(256) k_fc1_mma(const float* __restrict__ wq) {
    __shared__ __align__(16) unsigned char smbuf[30720];
    const uint32_t sb = smem_u32(smbuf);
    const int tid = threadIdx.x;
    const int wid = tid >> 5, lane = tid & 31;
    const int wm = wid & 3, wn = wid >> 2;
    const int ntile = blockIdx.x << 6;
    const int k0 = blockIdx.y << 9;

    float acc[2][4][4];
#pragma unroll
    for (int a = 0; a < 2; a++)
#pragma unroll
        for (int b = 0; b < 4; b++)
#pragma unroll
            for (int c = 0; c < 4; c++) acc[a][b][c] = 0.f;

    const uint32_t aAddrBase = sb + (uint32_t)((wm * 32 + (lane & 15)) * 80
                               + ((lane >> 4) & 1) * 16);
    const uint32_t bAddrBase = sb + (uint32_t)((wn * 32 + (lane & 7) + ((lane >> 4) ? 8 : 0)) * 80
                               + ((lane >> 3) & 1) * 16);

    const int arow = tid >> 3, asub = tid & 7;
    size_t abase = (size_t)arow * (FLATd / 2) + (k0 >> 1) + asub * 2;
    u64 hA[4], lA[4];
#pragma unroll
    for (int r = 0; r < 4; r++) {
        size_t ib = abase + (size_t)(r * 32) * (FLATd / 2);
        hA[r] = *(const u64*)(g_x_hi + ib);
        lA[r] = *(const u64*)(g_x_lo + ib);
    }
    float4 fB[2];
#pragma unroll
    for (int r = 0; r < 2; r++) {
        int i = tid + r * 256;
        fB[r] = *(const float4*)(wq + (size_t)(ntile + (i >> 3)) * FLATd + k0 + (i & 7) * 4);
    }

    for (int it = 0; it < 16; it++) {
#pragma unroll
        for (int r = 0; r < 4; r++) {
            uint32_t addr = (uint32_t)((arow + r * 32) * 80 + asub * 8);
            sts64(sb + FA_HI + addr, hA[r]);
            sts64(sb + FA_LO + addr, lA[r]);
        }
#pragma unroll
        for (int r = 0; r < 2; r++) {
            int i = tid + r * 256;
            uint32_t addr = (uint32_t)((i >> 3) * 80 + (i & 7) * 8);
            uint32_t h0, l0, h1, l1;
            cvtpair(fB[r].x, fB[r].y, h0, l0);
            cvtpair(fB[r].z, fB[r].w, h1, l1);
            sts_v2(sb + FB_HI + addr, h0, h1);
            sts_v2(sb + FB_LO + addr, l0, l1);
        }
        __syncthreads();

        if (it < 15) {
            abase += 16;
#pragma unroll
            for (int r = 0; r < 4; r++) {
                size_t ib = abase + (size_t)(r * 32) * (FLATd / 2);
                hA[r] = *(const u64*)(g_x_hi + ib);
                lA[r] = *(const u64*)(g_x_lo + ib);
            }
            int knext = k0 + (it + 1) * 32;
#pragma unroll
            for (int r = 0; r < 2; r++) {
                int i = tid + r * 256;
                fB[r] = *(const float4*)(wq + (size_t)(ntile + (i >> 3)) * FLATd + knext + (i & 7) * 4);
            }
        }

#pragma unroll
        for (int ks = 0; ks < 2; ks++) {
            uint32_t Ah[2][4], Al[2][4], Bh[2][4], Bl[2][4];
#pragma unroll
            for (int mt = 0; mt < 2; mt++) {
                uint32_t a = aAddrBase + (uint32_t)(mt * 16 * 80 + ks * 32);
                ldm_x4(Ah[mt], a + FA_HI);
                ldm_x4(Al[mt], a + FA_LO);
            }
#pragma unroll
            for (int np = 0; np < 2; np++) {
                uint32_t a = bAddrBase + (uint32_t)(np * 16 * 80 + ks * 32);
                ldm_x4(Bh[np], a + FB_HI);
                ldm_x4(Bl[np], a + FB_LO);
            }
#pragma unroll
            for (int mt = 0; mt < 2; mt++)
#pragma unroll
                for (int np = 0; np < 2; np++)
#pragma unroll
                    for (int hf = 0; hf < 2; hf++) {
                        int nt = np * 2 + hf;
                        mma_bf16(acc[mt][nt], Ah[mt], Bh[np][hf * 2], Bh[np][hf * 2 + 1]);
                        mma_bf16(acc[mt][nt], Ah[mt], Bl[np][hf * 2], Bl[np][hf * 2 + 1]);
                        mma_bf16(acc[mt][nt], Al[mt], Bh[np][hf * 2], Bh[np][hf * 2 + 1]);
                    }
        }
        __syncthreads();
    }

    float* outp = g_h1part + (size_t)blockIdx.y * (Bsz * HIDd);
#pragma unroll
    for (int mt = 0; mt < 2; mt++) {
        int rrow = wm * 32 + mt * 16 + (lane >> 2);
#pragma unroll
        for (int nt = 0; nt < 4; nt++) {
            int ccol = ntile + wn * 32 + nt * 8 + (lane & 3) * 2;
            *(float2*)&outp[(size_t)rrow * HIDd + ccol] =
                make_float2(acc[mt][nt][0], acc[mt][nt][1]);
            *(float2*)&outp[(size_t)(rrow + 8) * HIDd + ccol] =
                make_float2(acc[mt][nt][2], acc[mt][nt][3]);
        }
    }
}

// ---------------- fused: split-K reduce + bias + BN + ReLU + fc2 ----------------
__global__ void k_fc2f(const float* __restrict__ fb,
                       const float* __restrict__ bng,
                       const float* __restrict__ bnb,
                       const float* __restrict__ w2,
                       const float* __restrict__ b2,
                       float* __restrict__ out) {
    int b = blockIdx.x, tid = threadIdx.x;
    const float bns = rsqrtf(1.f + 1e-5f);
    float a0 = 0.f, a1 = 0.f;
    for (int o = tid; o < HIDd; o += 256) {
        float s = 0.f;
#pragma unroll
        for (int p = 0; p < SPLITK; p++)
            s += g_h1part[(size_t)p * (Bsz * HIDd) + (size_t)b * HIDd + o];
        float val = (s + fb[o]) * (bng[o] * bns) + bnb[o];
        val = fmaxf(val, 0.f);
        a0 += val * w2[o];
        a1 += val * w2[HIDd + o];
    }
    __shared__ float r0[256], r1[256];
    r0[tid] = a0; r1[tid] = a1;
    __syncthreads();
    for (int s = 128; s > 0; s >>= 1) {
        if (tid < s) { r0[tid] += r0[tid + s]; r1[tid] += r1[tid + s]; }
        __syncthreads();
    }
    if (tid == 0) {
        out[b * 2 + 0] = r0[0] + b2[0];
        out[b * 2 + 1] = r1[0] + b2[1];
    }
}

extern "C" void kernel_launch(void* const* d_in, const int* in_sizes, int n_in,
                              void* d_out, int out_size) {
    const float* x       = (const float*)d_in[0];
    const int*   ei      = (const int*)  d_in[1];
    const float* eattr   = (const float*)d_in[2];
    const float* tcn_w   = (const float*)d_in[3];
    const float* tcn_b   = (const float*)d_in[4];
    const float* lin_l_w = (const float*)d_in[5];
    const float* lin_l_b = (const float*)d_in[6];
    const float* lin_e_w = (const float*)d_in[7];
    const float* lin_e_b = (const float*)d_in[8];
    const float* att     = (const float*)d_in[9];
    const float* fc1_w   = (const float*)d_in[10];
    const float* fc1_b   = (const float*)d_in[11];
    const float* bn_g    = (const float*)d_in[12];
    const float* bn_b    = (const float*)d_in[13];
    const float* fc2_w   = (const float*)d_in[14];
    const float* fc2_b   = (const float*)d_in[15];
    float* out = (float*)d_out;

    cudaFuncSetAttribute(k_tcnlinl, cudaFuncAttributeMaxDynamicSharedMemorySize, TL_SMEM);

    k_tcnlinl<<<Bsz + 1, 256, TL_SMEM>>>(x, tcn_w, tcn_b, lin_l_w, lin_l_b, ei);
    k_score<<<dim3(EE / 256, Bsz), 256>>>(ei, eattr, lin_e_w, lin_e_b, att);
    k_agg<<<dim3(NN, Bsz), 128>>>();
    k_fc1_mma<<<dim3(32, SPLITK), 256>>>(fc1_w);
    k_fc2f<<<Bsz, 256>>>(fc1_b, bn_g, bn_b, fc2_w, fc2_b, out);
}